// round 13
// baseline (speedup 1.0000x reference)
#include <cuda_runtime.h>
#include <cuda_bf16.h>
#include <cuda_fp16.h>
#include <cstddef>
#include <cstdint>

#define BB 4
#define CC 64
#define FF 256
#define TT 256

// ---- scratch (device globals; no allocation allowed) ----
__device__ uint32_t g_qf[BB*FF*TT*8];
__device__ uint32_t g_kf[BB*FF*TT*8];
__device__ uint32_t g_v [BB*FF*TT*8];
__device__ uint32_t g_qt[BB*FF*TT*8];
__device__ uint32_t g_kt[BB*FF*TT*8];
__device__ uint32_t g_fo[BB*FF*TT*8];
__device__ __nv_bfloat16 g_z[BB*CC*FF*TT];   // layout of x: [B,C,F,T], bf16

// ============================================================================
// base-ISA tensor helpers
// ============================================================================
__device__ __forceinline__ uint32_t smem_u32(const void* p) {
    uint32_t a;
    asm("{ .reg .u64 t; cvta.to.shared.u64 t, %1; cvt.u32.u64 %0, t; }" : "=r"(a) : "l"(p));
    return a;
}
__device__ __forceinline__ void mma16816(float* c, const uint32_t* a, const uint32_t* b) {
    asm volatile("mma.sync.aligned.m16n8k16.row.col.f32.bf16.bf16.f32 "
        "{%0,%1,%2,%3}, {%4,%5,%6,%7}, {%8,%9}, {%0,%1,%2,%3};"
        : "+f"(c[0]), "+f"(c[1]), "+f"(c[2]), "+f"(c[3])
        : "r"(a[0]), "r"(a[1]), "r"(a[2]), "r"(a[3]), "r"(b[0]), "r"(b[1]));
}
// fp16 in / fp16 accumulate: C = 2 packed half2 regs
__device__ __forceinline__ void mma16816_h(uint32_t* c, const uint32_t* a, const uint32_t* b) {
    asm volatile("mma.sync.aligned.m16n8k16.row.col.f16.f16.f16.f16 "
        "{%0,%1}, {%2,%3,%4,%5}, {%6,%7}, {%0,%1};"
        : "+r"(c[0]), "+r"(c[1])
        : "r"(a[0]), "r"(a[1]), "r"(a[2]), "r"(a[3]), "r"(b[0]), "r"(b[1]));
}
__device__ __forceinline__ void ldm_x4(uint32_t* r, uint32_t addr) {
    asm volatile("ldmatrix.sync.aligned.m8n8.x4.shared.b16 {%0,%1,%2,%3}, [%4];"
        : "=r"(r[0]), "=r"(r[1]), "=r"(r[2]), "=r"(r[3]) : "r"(addr));
}
__device__ __forceinline__ void ldm_x4_trans(uint32_t* r, uint32_t addr) {
    asm volatile("ldmatrix.sync.aligned.m8n8.x4.trans.shared.b16 {%0,%1,%2,%3}, [%4];"
        : "=r"(r[0]), "=r"(r[1]), "=r"(r[2]), "=r"(r[3]) : "r"(addr));
}
__device__ __forceinline__ void ldm_x2(uint32_t& r0, uint32_t& r1, uint32_t addr) {
    asm volatile("ldmatrix.sync.aligned.m8n8.x2.shared.b16 {%0,%1}, [%2];"
        : "=r"(r0), "=r"(r1) : "r"(addr));
}
__device__ __forceinline__ void ldm_x2_trans(uint32_t& r0, uint32_t& r1, uint32_t addr) {
    asm volatile("ldmatrix.sync.aligned.m8n8.x2.trans.shared.b16 {%0,%1}, [%2];"
        : "=r"(r0), "=r"(r1) : "r"(addr));
}
__device__ __forceinline__ uint32_t bfpack(float a, float b) {
    __nv_bfloat162 h = __floats2bfloat162_rn(a, b);
    return *(uint32_t*)&h;
}
__device__ __forceinline__ float2 bfunpack(uint32_t u) {
    return __bfloat1622float2(*(__nv_bfloat162*)&u);
}
__device__ __forceinline__ uint32_t hpack(float a, float b) {
    __half2 h = __floats2half2_rn(a, b);
    return *(uint32_t*)&h;
}
__device__ __forceinline__ float2 hunpack(uint32_t u) {
    return __half22float2(*(__half2*)&u);
}

// ============================================================================
// K1: projections on HMMA.  (unchanged — working since R6)
// ============================================================================
#define PROJ_CS 33792
#define PROJ_DSMEM (33792 + 45056)

__global__ void __launch_bounds__(256) k_proj_mma(
    const float* __restrict__ x,
    const float* __restrict__ wf, const float* __restrict__ fg, const float* __restrict__ fb,
    const float* __restrict__ fm, const float* __restrict__ fv, const float* __restrict__ fa,
    const float* __restrict__ wt, const float* __restrict__ tg, const float* __restrict__ tb,
    const float* __restrict__ tm, const float* __restrict__ tv, const float* __restrict__ ta)
{
    extern __shared__ char psm[];
    __shared__ __align__(16) char ws[80 * 144];
    __shared__ float bs[80], posw[80], slw[80];

    const int tid = threadIdx.x;
    const int wid = tid >> 5, lane = tid & 31;
    const uint32_t sxs = smem_u32(psm);
    const uint32_t sws = smem_u32(ws);

    for (int i = tid; i < 80 * 64; i += 256) {
        int o = i >> 6, c = i & 63;
        float g, b_, m, v, w;
        if (o < 48) { g = fg[o]; b_ = fb[o]; m = fm[o]; v = fv[o]; w = wf[o * 64 + c]; }
        else { int oo = o - 48; g = tg[oo]; b_ = tb[oo]; m = tm[oo]; v = tv[oo]; w = wt[oo * 64 + c]; }
        float inv = g * rsqrtf(v + 1e-5f);
        *(__nv_bfloat16*)(ws + o * 144 + c * 2) = __float2bfloat16_rn(w * inv);
        if (c == 0) {
            float slope = (o < 48) ? fa[o] : ta[o - 48];
            float sc = (o < 48) ? ((o % 3 == 0) ? 0.25f : 1.f)
                                : ((((o - 48) & 1) == 0) ? 0.25f : 1.f);
            bs[o] = b_ - m * inv;
            posw[o] = sc;
            slw[o] = slope * sc;
        }
    }

    const int bf = blockIdx.x;
    const int b = bf >> 8, f = bf & 255;
    {
        const int c = tid >> 2, q = tid & 3;
        const float* xp = x + ((size_t)b << 22) + ((size_t)c << 16) + (size_t)f * 256 + q * 64;
        char* row = psm + c * 528 + q * 128;
        #pragma unroll
        for (int j = 0; j < 8; j++) {
            float4 v0 = ((const float4*)xp)[2 * j];
            float4 v1 = ((const float4*)xp)[2 * j + 1];
            *(uint4*)(row + j * 16) = make_uint4(bfpack(v0.x, v0.y), bfpack(v0.z, v0.w),
                                                 bfpack(v1.x, v1.y), bfpack(v1.z, v1.w));
        }
    }
    __syncthreads();

    uint32_t af[2][4][4];
    {
        const int cr = (lane & 7) + ((lane >> 4) << 3);
        const int tof = ((lane >> 3) & 1) * 8;
        #pragma unroll
        for (int m = 0; m < 2; m++) {
            const int t0 = (2 * wid + m) * 16;
            #pragma unroll
            for (int ksp = 0; ksp < 4; ksp++)
                ldm_x4_trans(af[m][ksp], sxs + (uint32_t)((ksp * 16 + cr) * 528 + (t0 + tof) * 2));
        }
    }

    #pragma unroll 1
    for (int nt = 0; nt < 10; nt++) {
        uint32_t bfr[4][2];
        #pragma unroll
        for (int ksp = 0; ksp < 4; ksp++)
            ldm_x2(bfr[ksp][0], bfr[ksp][1],
                   sws + (uint32_t)((nt * 8 + (lane & 7)) * 144 + (ksp * 16 + ((lane >> 3) & 1) * 8) * 2));

        const int n0 = nt * 8 + (lane & 3) * 2;
        const float b0 = bs[n0], b1 = bs[n0 + 1];
        const float p0 = posw[n0], p1 = posw[n0 + 1];
        const float s0 = slw[n0], s1 = slw[n0 + 1];
        const int pairidx = nt * 4 + (lane & 3);

        #pragma unroll
        for (int m = 0; m < 2; m++) {
            float cfr[4] = {0.f, 0.f, 0.f, 0.f};
            #pragma unroll
            for (int ksp = 0; ksp < 4; ksp++) mma16816(cfr, af[m][ksp], bfr[ksp]);

            float r0 = cfr[0] + b0, r1 = cfr[1] + b1, r2 = cfr[2] + b0, r3 = cfr[3] + b1;
            r0 = (r0 >= 0.f) ? r0 * p0 : r0 * s0;
            r1 = (r1 >= 0.f) ? r1 * p1 : r1 * s1;
            r2 = (r2 >= 0.f) ? r2 * p0 : r2 * s0;
            r3 = (r3 >= 0.f) ? r3 * p1 : r3 * s1;

            const int tlo = (2 * wid + m) * 16 + (lane >> 2);
            *(uint32_t*)(psm + PROJ_CS + tlo * 176 + pairidx * 4) = bfpack(r0, r1);
            *(uint32_t*)(psm + PROJ_CS + (tlo + 8) * 176 + pairidx * 4) = bfpack(r2, r3);
        }
    }
    __syncthreads();

    {
        const int t = tid;
        uint32_t pr[40];
        const uint4* crow = (const uint4*)(psm + PROJ_CS + t * 176);
        #pragma unroll
        for (int j = 0; j < 10; j++) {
            uint4 u = crow[j];
            pr[4*j] = u.x; pr[4*j+1] = u.y; pr[4*j+2] = u.z; pr[4*j+3] = u.w;
        }
        uint32_t v16[80];
        #pragma unroll
        for (int j = 0; j < 40; j++) { v16[2*j] = pr[j] & 0xffffu; v16[2*j+1] = pr[j] >> 16; }

        const size_t pos = (size_t)bf * 256 + t;
        uint32_t o0[8], o1[8], o2[8], o3[8], o4[8];
        #pragma unroll
        for (int j = 0; j < 8; j++) {
            o0[j] = v16[6*j]     | (v16[6*j + 3] << 16);
            o1[j] = v16[6*j + 1] | (v16[6*j + 4] << 16);
            o2[j] = v16[6*j + 2] | (v16[6*j + 5] << 16);
            o3[j] = v16[48 + 4*j]     | (v16[48 + 4*j + 2] << 16);
            o4[j] = v16[48 + 4*j + 1] | (v16[48 + 4*j + 3] << 16);
        }
        ((uint4*)g_qf)[pos*2]   = make_uint4(o0[0], o0[1], o0[2], o0[3]);
        ((uint4*)g_qf)[pos*2+1] = make_uint4(o0[4], o0[5], o0[6], o0[7]);
        ((uint4*)g_kf)[pos*2]   = make_uint4(o1[0], o1[1], o1[2], o1[3]);
        ((uint4*)g_kf)[pos*2+1] = make_uint4(o1[4], o1[5], o1[6], o1[7]);
        ((uint4*)g_v )[pos*2]   = make_uint4(o2[0], o2[1], o2[2], o2[3]);
        ((uint4*)g_v )[pos*2+1] = make_uint4(o2[4], o2[5], o2[6], o2[7]);
        ((uint4*)g_qt)[pos*2]   = make_uint4(o3[0], o3[1], o3[2], o3[3]);
        ((uint4*)g_qt)[pos*2+1] = make_uint4(o3[4], o3[5], o3[6], o3[7]);
        ((uint4*)g_kt)[pos*2]   = make_uint4(o4[0], o4[1], o4[2], o4[3]);
        ((uint4*)g_kt)[pos*2+1] = make_uint4(o4[4], o4[5], o4[6], o4[7]);
    }
}

// ============================================================================
// K2: frequency attention (HMMA, bf16 scratch).  (unchanged from R6)
// ============================================================================
__global__ void __launch_bounds__(128) k_fattn_mma()
{
    __shared__ __align__(16) char qs[256 * 48];
    __shared__ __align__(16) char ks[256 * 48];
    __shared__ __align__(16) char vs[256 * 48];

    const int bt = blockIdx.x;
    const int b = bt >> 8, t = bt & 255;
    const int tid = threadIdx.x;
    const int wid = tid >> 5, lane = tid & 31;
    const uint32_t svs = smem_u32(vs);

    {
        const uint2* gq = (const uint2*)g_qf + ((size_t)b * 65536 + t) * 4;
        const uint2* gk = (const uint2*)g_kf + ((size_t)b * 65536 + t) * 4;
        const uint2* gv = (const uint2*)g_v  + ((size_t)b * 65536 + t) * 4;
        #pragma unroll
        for (int i = tid; i < 1024; i += 128) {
            const int r = i >> 2, q = i & 3;
            const size_t so = (size_t)r * 1024 + q;
            *(uint2*)(qs + r * 48 + q * 8) = gq[so];
            *(uint2*)(ks + r * 48 + q * 8) = gk[so];
            *(uint2*)(vs + r * 48 + q * 8) = gv[so];
        }
    }
    __syncthreads();

    uint32_t qa[4][4];
    {
        const uint32_t rb = (lane >> 2), cb = (lane & 3) * 4;
        #pragma unroll
        for (int mt = 0; mt < 4; mt++) {
            const uint32_t m0 = wid * 64 + mt * 16;
            qa[mt][0] = *(const uint32_t*)(qs + (m0 + rb) * 48 + cb);
            qa[mt][1] = *(const uint32_t*)(qs + (m0 + 8 + rb) * 48 + cb);
            qa[mt][2] = *(const uint32_t*)(qs + (m0 + rb) * 48 + cb + 16);
            qa[mt][3] = *(const uint32_t*)(qs + (m0 + 8 + rb) * 48 + cb + 16);
        }
    }

    float acc[4][2][4];
    float ls[4][2];
    #pragma unroll
    for (int mt = 0; mt < 4; mt++) {
        ls[mt][0] = ls[mt][1] = 0.f;
        #pragma unroll
        for (int nc = 0; nc < 2; nc++)
            #pragma unroll
            for (int k = 0; k < 4; k++) acc[mt][nc][k] = 0.f;
    }

    for (int yt = 0; yt < 8; yt++) {
        const int y0 = yt * 32;
        uint32_t kb[4][2];
        #pragma unroll
        for (int j = 0; j < 4; j++) {
            const char* a = ks + (y0 + 8 * j + (lane >> 2)) * 48 + (lane & 3) * 4;
            kb[j][0] = *(const uint32_t*)a;
            kb[j][1] = *(const uint32_t*)(a + 16);
        }
        uint32_t vb[2][2][2];
        #pragma unroll
        for (int kst = 0; kst < 2; kst++)
            #pragma unroll
            for (int nc = 0; nc < 2; nc++)
                ldm_x2_trans(vb[kst][nc][0], vb[kst][nc][1],
                             svs + (uint32_t)((y0 + 16 * kst + (lane & 15)) * 48 + nc * 16));

        #pragma unroll
        for (int mt = 0; mt < 4; mt++) {
            float s[4][4];
            #pragma unroll
            for (int j = 0; j < 4; j++) { s[j][0]=s[j][1]=s[j][2]=s[j][3]=0.f; }
            #pragma unroll
            for (int j = 0; j < 4; j++) mma16816(s[j], qa[mt], kb[j]);

            float p[4][4];
            #pragma unroll
            for (int j = 0; j < 4; j++) {
                p[j][0] = __expf(s[j][0]); p[j][1] = __expf(s[j][1]);
                p[j][2] = __expf(s[j][2]); p[j][3] = __expf(s[j][3]);
                ls[mt][0] += p[j][0] + p[j][1];
                ls[mt][1] += p[j][2] + p[j][3];
            }
            uint32_t pa0[4], pa1[4];
            pa0[0] = bfpack(p[0][0], p[0][1]); pa0[1] = bfpack(p[0][2], p[0][3]);
            pa0[2] = bfpack(p[1][0], p[1][1]); pa0[3] = bfpack(p[1][2], p[1][3]);
            pa1[0] = bfpack(p[2][0], p[2][1]); pa1[1] = bfpack(p[2][2], p[2][3]);
            pa1[2] = bfpack(p[3][0], p[3][1]); pa1[3] = bfpack(p[3][2], p[3][3]);
            #pragma unroll
            for (int nc = 0; nc < 2; nc++) {
                mma16816(acc[mt][nc], pa0, vb[0][nc]);
                mma16816(acc[mt][nc], pa1, vb[1][nc]);
            }
        }
    }

    #pragma unroll
    for (int mt = 0; mt < 4; mt++) {
        float l0 = ls[mt][0], l1 = ls[mt][1];
        l0 += __shfl_xor_sync(0xffffffffu, l0, 1);
        l0 += __shfl_xor_sync(0xffffffffu, l0, 2);
        l1 += __shfl_xor_sync(0xffffffffu, l1, 1);
        l1 += __shfl_xor_sync(0xffffffffu, l1, 2);
        const float rl0 = __fdividef(1.f, l0), rl1 = __fdividef(1.f, l1);
        const int r0 = wid * 64 + mt * 16 + (lane >> 2);
        #pragma unroll
        for (int nc = 0; nc < 2; nc++) {
            const int pidx = nc * 4 + (lane & 3);
            g_fo[((size_t)b * 65536 + (size_t)r0 * 256 + t) * 8 + pidx] =
                bfpack(acc[mt][nc][0] * rl0, acc[mt][nc][1] * rl0);
            g_fo[((size_t)b * 65536 + (size_t)(r0 + 8) * 256 + t) * 8 + pidx] =
                bfpack(acc[mt][nc][2] * rl1, acc[mt][nc][3] * rl1);
        }
    }
}

// ============================================================================
// K3: causal time attention + zproj fusion.  (unchanged from R6)
// ============================================================================
#define TA_KS 12288
#define TA_VS 24576
#define TA_TS 36864
#define TA_WSP 55296
#define TA_BSP 59392
#define TA_ASP 59648
#define TA_DSMEM 59904

__global__ void __launch_bounds__(128) k_tattn_fused(
    const float* __restrict__ x, const float* __restrict__ wp,
    const float* __restrict__ pg, const float* __restrict__ pb,
    const float* __restrict__ pm, const float* __restrict__ pv,
    const float* __restrict__ pa)
{
    extern __shared__ char dsm[];
    char* qs = dsm;
    char* ks = dsm + TA_KS;
    char* vs = dsm + TA_VS;
    float* ts = (float*)(dsm + TA_TS);
    float* wsp = (float*)(dsm + TA_WSP);
    float* bsp = (float*)(dsm + TA_BSP);
    float* asp = (float*)(dsm + TA_ASP);

    const int bf = blockIdx.x;
    const int b = bf >> 8, f = bf & 255;
    const int tid = threadIdx.x;
    const int wid = tid >> 5, lane = tid & 31;
    const uint32_t svs = smem_u32(vs);

    {
        const uint2* gq = (const uint2*)g_qt + (size_t)bf * 1024;
        const uint2* gk = (const uint2*)g_kt + (size_t)bf * 1024;
        const uint2* gv = (const uint2*)g_fo + (size_t)bf * 1024;
        #pragma unroll
        for (int i = tid; i < 1024; i += 128) {
            const int r = i >> 2, q = i & 3;
            *(uint2*)(qs + r * 48 + q * 8) = gq[i];
            *(uint2*)(ks + r * 48 + q * 8) = gk[i];
            *(uint2*)(vs + r * 48 + q * 8) = gv[i];
        }
        for (int i = tid; i < 1024; i += 128) {
            const int o = i >> 4, k = i & 15;
            float inv = pg[o] * rsqrtf(pv[o] + 1e-5f);
            wsp[o * 16 + k] = wp[o * 16 + k] * inv;
            if (k == 0) { bsp[o] = pb[o] - pm[o] * inv; asp[o] = pa[o]; }
        }
    }
    __syncthreads();

    #pragma unroll 1
    for (int i = 0; i < 4; i++) {
        const int mt = wid + 4 * i;
        const int m0 = mt * 16;
        uint32_t qa[4];
        {
            const uint32_t rb = (lane >> 2), cb = (lane & 3) * 4;
            qa[0] = *(const uint32_t*)(qs + (m0 + rb) * 48 + cb);
            qa[1] = *(const uint32_t*)(qs + (m0 + 8 + rb) * 48 + cb);
            qa[2] = *(const uint32_t*)(qs + (m0 + rb) * 48 + cb + 16);
            qa[3] = *(const uint32_t*)(qs + (m0 + 8 + rb) * 48 + cb + 16);
        }
        float acc[2][4] = {{0.f,0.f,0.f,0.f},{0.f,0.f,0.f,0.f}};
        float ls0 = 0.f, ls1 = 0.f;
        const int nyt = (mt >> 1) + 1;

        for (int yt = 0; yt < nyt; yt++) {
            const int y0 = yt * 32;
            uint32_t kb[4][2];
            #pragma unroll
            for (int j = 0; j < 4; j++) {
                const char* a = ks + (y0 + 8 * j + (lane >> 2)) * 48 + (lane & 3) * 4;
                kb[j][0] = *(const uint32_t*)a;
                kb[j][1] = *(const uint32_t*)(a + 16);
            }
            uint32_t vb[2][2][2];
            #pragma unroll
            for (int kst = 0; kst < 2; kst++)
                #pragma unroll
                for (int nc = 0; nc < 2; nc++)
                    ldm_x2_trans(vb[kst][nc][0], vb[kst][nc][1],
                                 svs + (uint32_t)((y0 + 16 * kst + (lane & 15)) * 48 + nc * 16));

            float s[4][4];
            #pragma unroll
            for (int j = 0; j < 4; j++) { s[j][0]=s[j][1]=s[j][2]=s[j][3]=0.f; }
            #pragma unroll
            for (int j = 0; j < 4; j++) mma16816(s[j], qa, kb[j]);

            if (yt == nyt - 1) {
                const int r0 = m0 + (lane >> 2);
                #pragma unroll
                for (int j = 0; j < 4; j++) {
                    const int cb2 = y0 + 8 * j + (lane & 3) * 2;
                    if (cb2     > r0)     s[j][0] = -1e30f;
                    if (cb2 + 1 > r0)     s[j][1] = -1e30f;
                    if (cb2     > r0 + 8) s[j][2] = -1e30f;
                    if (cb2 + 1 > r0 + 8) s[j][3] = -1e30f;
                }
            }

            float p[4][4];
            #pragma unroll
            for (int j = 0; j < 4; j++) {
                p[j][0] = __expf(s[j][0]); p[j][1] = __expf(s[j][1]);
                p[j][2] = __expf(s[j][2]); p[j][3] = __expf(s[j][3]);
                ls0 += p[j][0] + p[j][1];
                ls1 += p[j][2] + p[j][3];
            }
            uint32_t pa0[4], pa1[4];
            pa0[0] = bfpack(p[0][0], p[0][1]); pa0[1] = bfpack(p[0][2], p[0][3]);
            pa0[2] = bfpack(p[1][0], p[1][1]); pa0[3] = bfpack(p[1][2], p[1][3]);
            pa1[0] = bfpack(p[2][0], p[2][1]); pa1[1] = bfpack(p[2][2], p[2][3]);
            pa1[2] = bfpack(p[3][0], p[3][1]); pa1[3] = bfpack(p[3][2], p[3][3]);
            #pragma unroll
            for (int nc = 0; nc < 2; nc++) {
                mma16816(acc[nc], pa0, vb[0][nc]);
                mma16816(acc[nc], pa1, vb[1][nc]);
            }
        }

        ls0 += __shfl_xor_sync(0xffffffffu, ls0, 1);
        ls0 += __shfl_xor_sync(0xffffffffu, ls0, 2);
        ls1 += __shfl_xor_sync(0xffffffffu, ls1, 1);
        ls1 += __shfl_xor_sync(0xffffffffu, ls1, 2);
        const float rl0 = __fdividef(1.f, ls0), rl1 = __fdividef(1.f, ls1);
        const int r0 = m0 + (lane >> 2);
        #pragma unroll
        for (int nc = 0; nc < 2; nc++) {
            const int col = 8 * nc + (lane & 3) * 2;
            *(float2*)(ts + r0 * 18 + col) = make_float2(acc[nc][0] * rl0, acc[nc][1] * rl0);
            *(float2*)(ts + (r0 + 8) * 18 + col) = make_float2(acc[nc][2] * rl1, acc[nc][3] * rl1);
        }
    }
    __syncthreads();

    #pragma unroll
    for (int pp = 0; pp < 2; pp++) {
        const int t = tid + pp * 128;
        float tv[16];
        const float* tr = ts + t * 18;
        #pragma unroll
        for (int j = 0; j < 8; j++) {
            float2 u = *(const float2*)(tr + 2 * j);
            tv[2*j] = u.x; tv[2*j+1] = u.y;
        }
        const float* xr = x + ((size_t)b << 22) + (size_t)f * 256 + t;
        __nv_bfloat16* zr = g_z + ((size_t)b << 22) + (size_t)f * 256 + t;
        #pragma unroll 4
        for (int c = 0; c < 64; c++) {
            const float* wr = wsp + c * 16;
            float s0 = 0.f, s1 = 0.f, s2 = 0.f, s3 = 0.f;
            #pragma unroll
            for (int j = 0; j < 4; j++) {
                s0 += wr[4*j]   * tv[4*j];
                s1 += wr[4*j+1] * tv[4*j+1];
                s2 += wr[4*j+2] * tv[4*j+2];
                s3 += wr[4*j+3] * tv[4*j+3];
            }
            float r = bsp[c] + ((s0 + s1) + (s2 + s3));
            r = (r >= 0.f) ? r : asp[c] * r;
            zr[(size_t)c << 16] = __float2bfloat16_rn(r + xr[(size_t)c << 16]);
        }
    }
}

// ============================================================================
// K4: LN + FFN, fp16 HMMA.  R12: LDSM-bandwidth fix.
// 256 threads / 8 warps; warp owns 32 rows (2 m-tiles) -> every weight
// B-fragment feeds 4 MMAs (2m x 2n): total weight smem traffic HALVED
// (L1 was 73% busy).  GELU done IN PLACE on c1 (its pair-reg layout is
// exactly GEMM2's A-fragment), eliminating the a2 array.
// Hard-sigmoid GELU + biases folded into accumulator init (R11, proven).
// ============================================================================
#define OFF_A  0
#define OFF_W1 36864
#define OFF_W2 92160
#define FFN_DSMEM 142336

__global__ void __launch_bounds__(256) k_ffn_hmma(
    const float* __restrict__ x,
    const float* __restrict__ lnw, const float* __restrict__ lnb,
    const float* __restrict__ w1, const float* __restrict__ b1,
    const float* __restrict__ w2, const float* __restrict__ b2,
    const float* __restrict__ gamma, float* __restrict__ out)
{
    extern __shared__ char sm[];
    __shared__ uint32_t s_b1h2[192];    // b1 as half2 pairs
    __shared__ uint32_t s_b2h2[32];     // b2 as half2 pairs
    __shared__ float s_lnw[64], s_lnb[64], s_gm[64];

    const int tid = threadIdx.x;
    const int wid = tid >> 5;
    const int lane = tid & 31;
    const uint32_t sb = smem_u32(sm);

    for (int i = tid; i < 384 * 64; i += 256) {
        int o = i >> 6, c = i & 63;
        *(__half*)(sm + OFF_W1 + o * 144 + c * 2) = __float2half_rn(w1[i]);
    }
    for (int i = tid; i < 64 * 384; i += 256) {
        int c = i / 384, e = i % 384;
        *(__half*)(sm + OFF_W2 + c * 784 + e * 2) = __float2half_rn(w2[i]);
    }
    if (tid < 192) s_b1h2[tid] = hpack(b1[2 * tid], b1[2 * tid + 1]);
    if (tid < 32)  s_b2h2[tid] = hpack(b2[2 * tid], b2[2 * tid + 1]);
    if (tid < 64) { s_lnw[tid] = lnw[tid]; s_lnb[tid] = lnb[tid]; s_gm[tid] = gamma[tid]; }
    __syncthreads();

    const __half2 kA = __floats2half2_rn(0.4255f, 0.4255f);
    const __half2 kH = __floats2half2_rn(0.5f, 0.5f);

    for (int tile = blockIdx.x; tile < 1024; tile += 148) {
        const int g0 = tile * 256;
        const int b = g0 >> 16;
        const int rbase = g0 & 65535;

        // ---- LN: 1 thread per position (warp-local rows) -> A smem fp16 ----
        {
            const int p = tid;
            const uint4* zp = (const uint4*)(g_z + ((size_t)b << 22) + (size_t)(rbase + p) * 64);
            uint32_t raw[32];
            float s = 0.f, ss = 0.f;
            #pragma unroll
            for (int j = 0; j < 8; j++) {
                uint4 u = zp[j];
                raw[4*j] = u.x; raw[4*j+1] = u.y; raw[4*j+2] = u.z; raw[4*j+3] = u.w;
                float2 f0 = bfunpack(u.x), f1 = bfunpack(u.y), f2 = bfunpack(u.z), f3 = bfunpack(u.w);
                s  += (f0.x + f0.y) + (f1.x + f1.y) + (f2.x + f2.y) + (f3.x + f3.y);
                ss += (f0.x*f0.x + f0.y*f0.y) + (f1.x*f1.x + f1.y*f1.y)
                    + (f2.x*f2.x + f2.y*f2.y) + (f3.x*f3.x + f3.y*f3.y);
            }
            float mu = s * (1.f / 64.f);
            float var = ss * (1.f / 64.f) - mu * mu;
            float rstd = rsqrtf(var + 1e-6f);

            char* ap = sm + OFF_A + p * 144;
            #pragma unroll
            for (int q = 0; q < 8; q++) {
                uint32_t pk[4];
                #pragma unroll
                for (int jj = 0; jj < 4; jj++) {
                    int pj = q * 4 + jj;        // pair index 0..31
                    float2 fv = bfunpack(raw[pj]);
                    int c0 = 2 * pj;
                    float a0 = (fv.x - mu) * rstd * s_lnw[c0]     + s_lnb[c0];
                    float a1 = (fv.y - mu) * rstd * s_lnw[c0 + 1] + s_lnb[c0 + 1];
                    pk[jj] = hpack(a0, a1);
                }
                *(uint4*)(ap + q * 16) = make_uint4(pk[0], pk[1], pk[2], pk[3]);
            }
        }
        __syncwarp();

        // ---- A fragments: 2 m-tiles per warp ----
        uint32_t af[2][4][4];
        {
            #pragma unroll
            for (int m = 0; m < 2; m++) {
                const int arow = (2 * wid + m) * 16 + (lane & 7) + ((lane >> 3) & 1) * 8;
                #pragma unroll
                for (int ksp = 0; ksp < 4; ksp++) {
                    uint32_t acol = ksp * 16 + (lane >> 4) * 8;
                    ldm_x4(af[m][ksp], sb + OFF_A + arow * 144 + acol * 2);
                }
            }
        }

        // c2 accumulators (2 m-tiles), initialized with b2
        uint32_t c2[2][8][2];
        #pragma unroll
        for (int m = 0; m < 2; m++)
            #pragma unroll
            for (int i = 0; i < 8; i++) {
                uint32_t bv = s_b2h2[i * 4 + (lane & 3)];
                c2[m][i][0] = bv; c2[m][i][1] = bv;
            }

        #pragma unroll 1
        for (int ch = 0; ch < 6; ch++) {
            uint32_t c1[2][8][2];
            #pragma unroll
            for (int m = 0; m < 2; m++)
                #pragma unroll
                for (int i = 0; i < 8; i++) {
                    uint32_t bv = s_b1h2[ch * 32 + i * 4 + (lane & 3)];
                    c1[m][i][0] = bv; c1[m][i][1] = bv;
                }

            // GEMM1: each weight frag feeds 2m x 2n = 4 MMAs
            #pragma unroll
            for (int ksp = 0; ksp < 4; ksp++) {
                #pragma unroll
                for (int ntp = 0; ntp < 4; ntp++) {
                    uint32_t brow = (uint32_t)(ch * 64 + ntp * 16 + ((lane >> 4) & 1) * 8 + (lane & 7));
                    uint32_t bcol = (uint32_t)(ksp * 16 + ((lane >> 3) & 1) * 8);
                    uint32_t bfr[4];
                    ldm_x4(bfr, sb + OFF_W1 + brow * 144 + bcol * 2);
                    #pragma unroll
                    for (int m = 0; m < 2; m++) {
                        mma16816_h(c1[m][2 * ntp],     af[m][ksp], bfr);
                        mma16816_h(c1[m][2 * ntp + 1], af[m][ksp], bfr + 2);
                    }
                }
            }

            // hard-sigmoid GELU IN PLACE (c1 pair-layout == GEMM2 A-frag)
            #pragma unroll
            for (int m = 0; m < 2; m++)
                #pragma unroll
                for (int nt = 0; nt < 8; nt++)
                    #pragma unroll
                    for (int rr = 0; rr < 2; rr++) {
                        __half2 d = *(__half2*)&c1[m][nt][rr];
                        __half2 sg = __hfma2_sat(d, kA, kH);
                        __half2 hh = __hmul2(d, sg);
                        c1[m][nt][rr] = *(uint32_t*)&hh;
                    }

            // GEMM2: A-operand taken directly from c1 (contiguous 4 regs)
            #pragma unroll
            for (int j = 0; j < 4; j++) {
                #pragma unroll
                for (int ntp = 0; ntp < 4; ntp++) {
                    uint32_t brow = (uint32_t)(ntp * 16 + ((lane >> 4) & 1) * 8 + (lane & 7));
                    uint32_t bcol = (uint32_t)(ch * 64 + j * 16 + ((lane >> 3) & 1) * 8);
                    uint32_t bfr[4];
                    ldm_x4(bfr, sb + OFF_W2 + brow * 784 + bcol * 2);
                    #pragma unroll
                    for (int m = 0; m < 2; m++) {
                        mma16816_h(c2[m][2 * ntp],     &c1[m][2 * j][0], bfr);
                        mma16816_h(c2[m][2 * ntp + 1], &c1[m][2 * j][0], bfr + 2);
                    }
                }
            }
        }

        // ---- epilogue: out = x + gamma * c2  (b2 already inside c2) ----
        #pragma unroll
        for (int m = 0; m < 2; m++) {
            const int p0 = rbase + (2 * wid + m) * 16 + (lane >> 2);
            const int p1 = p0 + 8;
            const size_t bb = (size_t)b << 22;
            #pragma unroll
            for (int nt2 = 0; nt2 < 8; nt2++) {
                const int c0 = nt2 * 8 + (lane & 3) * 2;
                const int c1i = c0 + 1;
                float2 r0 = hunpack(c2[m][nt2][0]);
                float2 r1 = hunpack(c2[m][nt2][1]);
                const size_t a00 = bb + ((size_t)c0  << 16) + p0;
                const size_t a01 = bb + ((size_t)c1i << 16) + p0;
                const size_t a10 = bb + ((size_t)c0  << 16) + p1;
                const size_t a11 = bb + ((size_t)c1i << 16) + p1;
                out[a00] = x[a00] + s_gm[c0]  * r0.x;
                out[a01] = x[a01] + s_gm[c1i] * r0.y;
                out[a10] = x[a10] + s_gm[c0]  * r1.x;
                out[a11] = x[a11] + s_gm[c1i] * r1.y;
            }
        }
        __syncwarp();
    }
}

// ============================================================================
extern "C" void kernel_launch(void* const* d_in, const int* in_sizes, int n_in,
                              void* d_out, int out_size)
{
    const float* x   = (const float*)d_in[0];
    const float* wf  = (const float*)d_in[1];
    const float* f_g = (const float*)d_in[2];
    const float* f_b = (const float*)d_in[3];
    const float* f_m = (const float*)d_in[4];
    const float* f_v = (const float*)d_in[5];
    const float* f_a = (const float*)d_in[6];
    const float* wt  = (const float*)d_in[7];
    const float* t_g = (const float*)d_in[8];
    const float* t_b = (const float*)d_in[9];
    const float* t_m = (const float*)d_in[10];
    const float* t_v = (const float*)d_in[11];
    const float* t_a = (const float*)d_in[12];
    const float* wp  = (const float*)d_in[13];
    const float* p_g = (const float*)d_in[14];
    const float* p_b = (const float*)d_in[15];
    const float* p_m = (const float*)d_in[16];
    const float* p_v = (const float*)d_in[17];
    const float* p_a = (const float*)d_in[18];
    const float* lnw = (const float*)d_in[19];
    const float* lnb = (const float*)d_in[20];
    const float* w1  = (const float*)d_in[21];
    const float* b1  = (const float*)d_in[22];
    const float* w2  = (const float*)d_in[23];
    const float* b2  = (const float*)d_in[24];
    const float* gam = (const float*)d_in[25];
    float* out = (float*)d_out;

    cudaFuncSetAttribute(k_proj_mma, cudaFuncAttributeMaxDynamicSharedMemorySize, PROJ_DSMEM);
    cudaFuncSetAttribute(k_tattn_fused, cudaFuncAttributeMaxDynamicSharedMemorySize, TA_DSMEM);
    cudaFuncSetAttribute(k_ffn_hmma, cudaFuncAttributeMaxDynamicSharedMemorySize, FFN_DSMEM);

    k_proj_mma<<<BB * FF, 256, PROJ_DSMEM>>>(x, wf, f_g, f_b, f_m, f_v, f_a,
                                             wt, t_g, t_b, t_m, t_v, t_a);
    k_fattn_mma<<<BB * TT, 128>>>();
    k_tattn_fused<<<BB * FF, 128, TA_DSMEM>>>(x, wp, p_g, p_b, p_m, p_v, p_a);
    k_ffn_hmma<<<148, 256, FFN_DSMEM>>>(x, lnw, lnb, w1, b1, w2, b2, gam, out);
}

// round 14
// speedup vs baseline: 1.0278x; 1.0278x over previous
#include <cuda_runtime.h>
#include <cuda_bf16.h>
#include <cuda_fp16.h>
#include <cstddef>
#include <cstdint>

#define BB 4
#define CC 64
#define FF 256
#define TT 256

// ---- scratch (device globals; no allocation allowed) ----
__device__ uint32_t g_qf[BB*FF*TT*8];
__device__ uint32_t g_kf[BB*FF*TT*8];
__device__ uint32_t g_v [BB*FF*TT*8];
__device__ uint32_t g_qt[BB*FF*TT*8];
__device__ uint32_t g_kt[BB*FF*TT*8];
__device__ uint32_t g_fo[BB*FF*TT*8];
__device__ __nv_bfloat16 g_z[BB*CC*FF*TT];   // layout of x: [B,C,F,T], bf16

// ============================================================================
// base-ISA tensor helpers
// ============================================================================
__device__ __forceinline__ uint32_t smem_u32(const void* p) {
    uint32_t a;
    asm("{ .reg .u64 t; cvta.to.shared.u64 t, %1; cvt.u32.u64 %0, t; }" : "=r"(a) : "l"(p));
    return a;
}
__device__ __forceinline__ void mma16816(float* c, const uint32_t* a, const uint32_t* b) {
    asm volatile("mma.sync.aligned.m16n8k16.row.col.f32.bf16.bf16.f32 "
        "{%0,%1,%2,%3}, {%4,%5,%6,%7}, {%8,%9}, {%0,%1,%2,%3};"
        : "+f"(c[0]), "+f"(c[1]), "+f"(c[2]), "+f"(c[3])
        : "r"(a[0]), "r"(a[1]), "r"(a[2]), "r"(a[3]), "r"(b[0]), "r"(b[1]));
}
// fp16 in / fp16 accumulate: C = 2 packed half2 regs
__device__ __forceinline__ void mma16816_h(uint32_t* c, const uint32_t* a, const uint32_t* b) {
    asm volatile("mma.sync.aligned.m16n8k16.row.col.f16.f16.f16.f16 "
        "{%0,%1}, {%2,%3,%4,%5}, {%6,%7}, {%0,%1};"
        : "+r"(c[0]), "+r"(c[1])
        : "r"(a[0]), "r"(a[1]), "r"(a[2]), "r"(a[3]), "r"(b[0]), "r"(b[1]));
}
__device__ __forceinline__ void ldm_x4(uint32_t* r, uint32_t addr) {
    asm volatile("ldmatrix.sync.aligned.m8n8.x4.shared.b16 {%0,%1,%2,%3}, [%4];"
        : "=r"(r[0]), "=r"(r[1]), "=r"(r[2]), "=r"(r[3]) : "r"(addr));
}
__device__ __forceinline__ void ldm_x4_trans(uint32_t* r, uint32_t addr) {
    asm volatile("ldmatrix.sync.aligned.m8n8.x4.trans.shared.b16 {%0,%1,%2,%3}, [%4];"
        : "=r"(r[0]), "=r"(r[1]), "=r"(r[2]), "=r"(r[3]) : "r"(addr));
}
__device__ __forceinline__ void ldm_x2(uint32_t& r0, uint32_t& r1, uint32_t addr) {
    asm volatile("ldmatrix.sync.aligned.m8n8.x2.shared.b16 {%0,%1}, [%2];"
        : "=r"(r0), "=r"(r1) : "r"(addr));
}
__device__ __forceinline__ void ldm_x2_trans(uint32_t& r0, uint32_t& r1, uint32_t addr) {
    asm volatile("ldmatrix.sync.aligned.m8n8.x2.trans.shared.b16 {%0,%1}, [%2];"
        : "=r"(r0), "=r"(r1) : "r"(addr));
}
__device__ __forceinline__ uint32_t bfpack(float a, float b) {
    __nv_bfloat162 h = __floats2bfloat162_rn(a, b);
    return *(uint32_t*)&h;
}
__device__ __forceinline__ float2 bfunpack(uint32_t u) {
    return __bfloat1622float2(*(__nv_bfloat162*)&u);
}
__device__ __forceinline__ uint32_t hpack(float a, float b) {
    __half2 h = __floats2half2_rn(a, b);
    return *(uint32_t*)&h;
}
__device__ __forceinline__ float2 hunpack(uint32_t u) {
    return __half22float2(*(__half2*)&u);
}

// ============================================================================
// K1: projections on HMMA.  (unchanged — working since R6)
// ============================================================================
#define PROJ_CS 33792
#define PROJ_DSMEM (33792 + 45056)

__global__ void __launch_bounds__(256) k_proj_mma(
    const float* __restrict__ x,
    const float* __restrict__ wf, const float* __restrict__ fg, const float* __restrict__ fb,
    const float* __restrict__ fm, const float* __restrict__ fv, const float* __restrict__ fa,
    const float* __restrict__ wt, const float* __restrict__ tg, const float* __restrict__ tb,
    const float* __restrict__ tm, const float* __restrict__ tv, const float* __restrict__ ta)
{
    extern __shared__ char psm[];
    __shared__ __align__(16) char ws[80 * 144];
    __shared__ float bs[80], posw[80], slw[80];

    const int tid = threadIdx.x;
    const int wid = tid >> 5, lane = tid & 31;
    const uint32_t sxs = smem_u32(psm);
    const uint32_t sws = smem_u32(ws);

    for (int i = tid; i < 80 * 64; i += 256) {
        int o = i >> 6, c = i & 63;
        float g, b_, m, v, w;
        if (o < 48) { g = fg[o]; b_ = fb[o]; m = fm[o]; v = fv[o]; w = wf[o * 64 + c]; }
        else { int oo = o - 48; g = tg[oo]; b_ = tb[oo]; m = tm[oo]; v = tv[oo]; w = wt[oo * 64 + c]; }
        float inv = g * rsqrtf(v + 1e-5f);
        *(__nv_bfloat16*)(ws + o * 144 + c * 2) = __float2bfloat16_rn(w * inv);
        if (c == 0) {
            float slope = (o < 48) ? fa[o] : ta[o - 48];
            float sc = (o < 48) ? ((o % 3 == 0) ? 0.25f : 1.f)
                                : ((((o - 48) & 1) == 0) ? 0.25f : 1.f);
            bs[o] = b_ - m * inv;
            posw[o] = sc;
            slw[o] = slope * sc;
        }
    }

    const int bf = blockIdx.x;
    const int b = bf >> 8, f = bf & 255;
    {
        const int c = tid >> 2, q = tid & 3;
        const float* xp = x + ((size_t)b << 22) + ((size_t)c << 16) + (size_t)f * 256 + q * 64;
        char* row = psm + c * 528 + q * 128;
        #pragma unroll
        for (int j = 0; j < 8; j++) {
            float4 v0 = ((const float4*)xp)[2 * j];
            float4 v1 = ((const float4*)xp)[2 * j + 1];
            *(uint4*)(row + j * 16) = make_uint4(bfpack(v0.x, v0.y), bfpack(v0.z, v0.w),
                                                 bfpack(v1.x, v1.y), bfpack(v1.z, v1.w));
        }
    }
    __syncthreads();

    uint32_t af[2][4][4];
    {
        const int cr = (lane & 7) + ((lane >> 4) << 3);
        const int tof = ((lane >> 3) & 1) * 8;
        #pragma unroll
        for (int m = 0; m < 2; m++) {
            const int t0 = (2 * wid + m) * 16;
            #pragma unroll
            for (int ksp = 0; ksp < 4; ksp++)
                ldm_x4_trans(af[m][ksp], sxs + (uint32_t)((ksp * 16 + cr) * 528 + (t0 + tof) * 2));
        }
    }

    #pragma unroll 1
    for (int nt = 0; nt < 10; nt++) {
        uint32_t bfr[4][2];
        #pragma unroll
        for (int ksp = 0; ksp < 4; ksp++)
            ldm_x2(bfr[ksp][0], bfr[ksp][1],
                   sws + (uint32_t)((nt * 8 + (lane & 7)) * 144 + (ksp * 16 + ((lane >> 3) & 1) * 8) * 2));

        const int n0 = nt * 8 + (lane & 3) * 2;
        const float b0 = bs[n0], b1 = bs[n0 + 1];
        const float p0 = posw[n0], p1 = posw[n0 + 1];
        const float s0 = slw[n0], s1 = slw[n0 + 1];
        const int pairidx = nt * 4 + (lane & 3);

        #pragma unroll
        for (int m = 0; m < 2; m++) {
            float cfr[4] = {0.f, 0.f, 0.f, 0.f};
            #pragma unroll
            for (int ksp = 0; ksp < 4; ksp++) mma16816(cfr, af[m][ksp], bfr[ksp]);

            float r0 = cfr[0] + b0, r1 = cfr[1] + b1, r2 = cfr[2] + b0, r3 = cfr[3] + b1;
            r0 = (r0 >= 0.f) ? r0 * p0 : r0 * s0;
            r1 = (r1 >= 0.f) ? r1 * p1 : r1 * s1;
            r2 = (r2 >= 0.f) ? r2 * p0 : r2 * s0;
            r3 = (r3 >= 0.f) ? r3 * p1 : r3 * s1;

            const int tlo = (2 * wid + m) * 16 + (lane >> 2);
            *(uint32_t*)(psm + PROJ_CS + tlo * 176 + pairidx * 4) = bfpack(r0, r1);
            *(uint32_t*)(psm + PROJ_CS + (tlo + 8) * 176 + pairidx * 4) = bfpack(r2, r3);
        }
    }
    __syncthreads();

    {
        const int t = tid;
        uint32_t pr[40];
        const uint4* crow = (const uint4*)(psm + PROJ_CS + t * 176);
        #pragma unroll
        for (int j = 0; j < 10; j++) {
            uint4 u = crow[j];
            pr[4*j] = u.x; pr[4*j+1] = u.y; pr[4*j+2] = u.z; pr[4*j+3] = u.w;
        }
        uint32_t v16[80];
        #pragma unroll
        for (int j = 0; j < 40; j++) { v16[2*j] = pr[j] & 0xffffu; v16[2*j+1] = pr[j] >> 16; }

        const size_t pos = (size_t)bf * 256 + t;
        uint32_t o0[8], o1[8], o2[8], o3[8], o4[8];
        #pragma unroll
        for (int j = 0; j < 8; j++) {
            o0[j] = v16[6*j]     | (v16[6*j + 3] << 16);
            o1[j] = v16[6*j + 1] | (v16[6*j + 4] << 16);
            o2[j] = v16[6*j + 2] | (v16[6*j + 5] << 16);
            o3[j] = v16[48 + 4*j]     | (v16[48 + 4*j + 2] << 16);
            o4[j] = v16[48 + 4*j + 1] | (v16[48 + 4*j + 3] << 16);
        }
        ((uint4*)g_qf)[pos*2]   = make_uint4(o0[0], o0[1], o0[2], o0[3]);
        ((uint4*)g_qf)[pos*2+1] = make_uint4(o0[4], o0[5], o0[6], o0[7]);
        ((uint4*)g_kf)[pos*2]   = make_uint4(o1[0], o1[1], o1[2], o1[3]);
        ((uint4*)g_kf)[pos*2+1] = make_uint4(o1[4], o1[5], o1[6], o1[7]);
        ((uint4*)g_v )[pos*2]   = make_uint4(o2[0], o2[1], o2[2], o2[3]);
        ((uint4*)g_v )[pos*2+1] = make_uint4(o2[4], o2[5], o2[6], o2[7]);
        ((uint4*)g_qt)[pos*2]   = make_uint4(o3[0], o3[1], o3[2], o3[3]);
        ((uint4*)g_qt)[pos*2+1] = make_uint4(o3[4], o3[5], o3[6], o3[7]);
        ((uint4*)g_kt)[pos*2]   = make_uint4(o4[0], o4[1], o4[2], o4[3]);
        ((uint4*)g_kt)[pos*2+1] = make_uint4(o4[4], o4[5], o4[6], o4[7]);
    }
}

// ============================================================================
// K2: frequency attention (HMMA, bf16 scratch).  (unchanged from R6)
// ============================================================================
__global__ void __launch_bounds__(128) k_fattn_mma()
{
    __shared__ __align__(16) char qs[256 * 48];
    __shared__ __align__(16) char ks[256 * 48];
    __shared__ __align__(16) char vs[256 * 48];

    const int bt = blockIdx.x;
    const int b = bt >> 8, t = bt & 255;
    const int tid = threadIdx.x;
    const int wid = tid >> 5, lane = tid & 31;
    const uint32_t svs = smem_u32(vs);

    {
        const uint2* gq = (const uint2*)g_qf + ((size_t)b * 65536 + t) * 4;
        const uint2* gk = (const uint2*)g_kf + ((size_t)b * 65536 + t) * 4;
        const uint2* gv = (const uint2*)g_v  + ((size_t)b * 65536 + t) * 4;
        #pragma unroll
        for (int i = tid; i < 1024; i += 128) {
            const int r = i >> 2, q = i & 3;
            const size_t so = (size_t)r * 1024 + q;
            *(uint2*)(qs + r * 48 + q * 8) = gq[so];
            *(uint2*)(ks + r * 48 + q * 8) = gk[so];
            *(uint2*)(vs + r * 48 + q * 8) = gv[so];
        }
    }
    __syncthreads();

    uint32_t qa[4][4];
    {
        const uint32_t rb = (lane >> 2), cb = (lane & 3) * 4;
        #pragma unroll
        for (int mt = 0; mt < 4; mt++) {
            const uint32_t m0 = wid * 64 + mt * 16;
            qa[mt][0] = *(const uint32_t*)(qs + (m0 + rb) * 48 + cb);
            qa[mt][1] = *(const uint32_t*)(qs + (m0 + 8 + rb) * 48 + cb);
            qa[mt][2] = *(const uint32_t*)(qs + (m0 + rb) * 48 + cb + 16);
            qa[mt][3] = *(const uint32_t*)(qs + (m0 + 8 + rb) * 48 + cb + 16);
        }
    }

    float acc[4][2][4];
    float ls[4][2];
    #pragma unroll
    for (int mt = 0; mt < 4; mt++) {
        ls[mt][0] = ls[mt][1] = 0.f;
        #pragma unroll
        for (int nc = 0; nc < 2; nc++)
            #pragma unroll
            for (int k = 0; k < 4; k++) acc[mt][nc][k] = 0.f;
    }

    for (int yt = 0; yt < 8; yt++) {
        const int y0 = yt * 32;
        uint32_t kb[4][2];
        #pragma unroll
        for (int j = 0; j < 4; j++) {
            const char* a = ks + (y0 + 8 * j + (lane >> 2)) * 48 + (lane & 3) * 4;
            kb[j][0] = *(const uint32_t*)a;
            kb[j][1] = *(const uint32_t*)(a + 16);
        }
        uint32_t vb[2][2][2];
        #pragma unroll
        for (int kst = 0; kst < 2; kst++)
            #pragma unroll
            for (int nc = 0; nc < 2; nc++)
                ldm_x2_trans(vb[kst][nc][0], vb[kst][nc][1],
                             svs + (uint32_t)((y0 + 16 * kst + (lane & 15)) * 48 + nc * 16));

        #pragma unroll
        for (int mt = 0; mt < 4; mt++) {
            float s[4][4];
            #pragma unroll
            for (int j = 0; j < 4; j++) { s[j][0]=s[j][1]=s[j][2]=s[j][3]=0.f; }
            #pragma unroll
            for (int j = 0; j < 4; j++) mma16816(s[j], qa[mt], kb[j]);

            float p[4][4];
            #pragma unroll
            for (int j = 0; j < 4; j++) {
                p[j][0] = __expf(s[j][0]); p[j][1] = __expf(s[j][1]);
                p[j][2] = __expf(s[j][2]); p[j][3] = __expf(s[j][3]);
                ls[mt][0] += p[j][0] + p[j][1];
                ls[mt][1] += p[j][2] + p[j][3];
            }
            uint32_t pa0[4], pa1[4];
            pa0[0] = bfpack(p[0][0], p[0][1]); pa0[1] = bfpack(p[0][2], p[0][3]);
            pa0[2] = bfpack(p[1][0], p[1][1]); pa0[3] = bfpack(p[1][2], p[1][3]);
            pa1[0] = bfpack(p[2][0], p[2][1]); pa1[1] = bfpack(p[2][2], p[2][3]);
            pa1[2] = bfpack(p[3][0], p[3][1]); pa1[3] = bfpack(p[3][2], p[3][3]);
            #pragma unroll
            for (int nc = 0; nc < 2; nc++) {
                mma16816(acc[mt][nc], pa0, vb[0][nc]);
                mma16816(acc[mt][nc], pa1, vb[1][nc]);
            }
        }
    }

    #pragma unroll
    for (int mt = 0; mt < 4; mt++) {
        float l0 = ls[mt][0], l1 = ls[mt][1];
        l0 += __shfl_xor_sync(0xffffffffu, l0, 1);
        l0 += __shfl_xor_sync(0xffffffffu, l0, 2);
        l1 += __shfl_xor_sync(0xffffffffu, l1, 1);
        l1 += __shfl_xor_sync(0xffffffffu, l1, 2);
        const float rl0 = __fdividef(1.f, l0), rl1 = __fdividef(1.f, l1);
        const int r0 = wid * 64 + mt * 16 + (lane >> 2);
        #pragma unroll
        for (int nc = 0; nc < 2; nc++) {
            const int pidx = nc * 4 + (lane & 3);
            g_fo[((size_t)b * 65536 + (size_t)r0 * 256 + t) * 8 + pidx] =
                bfpack(acc[mt][nc][0] * rl0, acc[mt][nc][1] * rl0);
            g_fo[((size_t)b * 65536 + (size_t)(r0 + 8) * 256 + t) * 8 + pidx] =
                bfpack(acc[mt][nc][2] * rl1, acc[mt][nc][3] * rl1);
        }
    }
}

// ============================================================================
// K3: causal time attention + zproj fusion.  (unchanged from R6)
// ============================================================================
#define TA_KS 12288
#define TA_VS 24576
#define TA_TS 36864
#define TA_WSP 55296
#define TA_BSP 59392
#define TA_ASP 59648
#define TA_DSMEM 59904

__global__ void __launch_bounds__(128) k_tattn_fused(
    const float* __restrict__ x, const float* __restrict__ wp,
    const float* __restrict__ pg, const float* __restrict__ pb,
    const float* __restrict__ pm, const float* __restrict__ pv,
    const float* __restrict__ pa)
{
    extern __shared__ char dsm[];
    char* qs = dsm;
    char* ks = dsm + TA_KS;
    char* vs = dsm + TA_VS;
    float* ts = (float*)(dsm + TA_TS);
    float* wsp = (float*)(dsm + TA_WSP);
    float* bsp = (float*)(dsm + TA_BSP);
    float* asp = (float*)(dsm + TA_ASP);

    const int bf = blockIdx.x;
    const int b = bf >> 8, f = bf & 255;
    const int tid = threadIdx.x;
    const int wid = tid >> 5, lane = tid & 31;
    const uint32_t svs = smem_u32(vs);

    {
        const uint2* gq = (const uint2*)g_qt + (size_t)bf * 1024;
        const uint2* gk = (const uint2*)g_kt + (size_t)bf * 1024;
        const uint2* gv = (const uint2*)g_fo + (size_t)bf * 1024;
        #pragma unroll
        for (int i = tid; i < 1024; i += 128) {
            const int r = i >> 2, q = i & 3;
            *(uint2*)(qs + r * 48 + q * 8) = gq[i];
            *(uint2*)(ks + r * 48 + q * 8) = gk[i];
            *(uint2*)(vs + r * 48 + q * 8) = gv[i];
        }
        for (int i = tid; i < 1024; i += 128) {
            const int o = i >> 4, k = i & 15;
            float inv = pg[o] * rsqrtf(pv[o] + 1e-5f);
            wsp[o * 16 + k] = wp[o * 16 + k] * inv;
            if (k == 0) { bsp[o] = pb[o] - pm[o] * inv; asp[o] = pa[o]; }
        }
    }
    __syncthreads();

    #pragma unroll 1
    for (int i = 0; i < 4; i++) {
        const int mt = wid + 4 * i;
        const int m0 = mt * 16;
        uint32_t qa[4];
        {
            const uint32_t rb = (lane >> 2), cb = (lane & 3) * 4;
            qa[0] = *(const uint32_t*)(qs + (m0 + rb) * 48 + cb);
            qa[1] = *(const uint32_t*)(qs + (m0 + 8 + rb) * 48 + cb);
            qa[2] = *(const uint32_t*)(qs + (m0 + rb) * 48 + cb + 16);
            qa[3] = *(const uint32_t*)(qs + (m0 + 8 + rb) * 48 + cb + 16);
        }
        float acc[2][4] = {{0.f,0.f,0.f,0.f},{0.f,0.f,0.f,0.f}};
        float ls0 = 0.f, ls1 = 0.f;
        const int nyt = (mt >> 1) + 1;

        for (int yt = 0; yt < nyt; yt++) {
            const int y0 = yt * 32;
            uint32_t kb[4][2];
            #pragma unroll
            for (int j = 0; j < 4; j++) {
                const char* a = ks + (y0 + 8 * j + (lane >> 2)) * 48 + (lane & 3) * 4;
                kb[j][0] = *(const uint32_t*)a;
                kb[j][1] = *(const uint32_t*)(a + 16);
            }
            uint32_t vb[2][2][2];
            #pragma unroll
            for (int kst = 0; kst < 2; kst++)
                #pragma unroll
                for (int nc = 0; nc < 2; nc++)
                    ldm_x2_trans(vb[kst][nc][0], vb[kst][nc][1],
                                 svs + (uint32_t)((y0 + 16 * kst + (lane & 15)) * 48 + nc * 16));

            float s[4][4];
            #pragma unroll
            for (int j = 0; j < 4; j++) { s[j][0]=s[j][1]=s[j][2]=s[j][3]=0.f; }
            #pragma unroll
            for (int j = 0; j < 4; j++) mma16816(s[j], qa, kb[j]);

            if (yt == nyt - 1) {
                const int r0 = m0 + (lane >> 2);
                #pragma unroll
                for (int j = 0; j < 4; j++) {
                    const int cb2 = y0 + 8 * j + (lane & 3) * 2;
                    if (cb2     > r0)     s[j][0] = -1e30f;
                    if (cb2 + 1 > r0)     s[j][1] = -1e30f;
                    if (cb2     > r0 + 8) s[j][2] = -1e30f;
                    if (cb2 + 1 > r0 + 8) s[j][3] = -1e30f;
                }
            }

            float p[4][4];
            #pragma unroll
            for (int j = 0; j < 4; j++) {
                p[j][0] = __expf(s[j][0]); p[j][1] = __expf(s[j][1]);
                p[j][2] = __expf(s[j][2]); p[j][3] = __expf(s[j][3]);
                ls0 += p[j][0] + p[j][1];
                ls1 += p[j][2] + p[j][3];
            }
            uint32_t pa0[4], pa1[4];
            pa0[0] = bfpack(p[0][0], p[0][1]); pa0[1] = bfpack(p[0][2], p[0][3]);
            pa0[2] = bfpack(p[1][0], p[1][1]); pa0[3] = bfpack(p[1][2], p[1][3]);
            pa1[0] = bfpack(p[2][0], p[2][1]); pa1[1] = bfpack(p[2][2], p[2][3]);
            pa1[2] = bfpack(p[3][0], p[3][1]); pa1[3] = bfpack(p[3][2], p[3][3]);
            #pragma unroll
            for (int nc = 0; nc < 2; nc++) {
                mma16816(acc[nc], pa0, vb[0][nc]);
                mma16816(acc[nc], pa1, vb[1][nc]);
            }
        }

        ls0 += __shfl_xor_sync(0xffffffffu, ls0, 1);
        ls0 += __shfl_xor_sync(0xffffffffu, ls0, 2);
        ls1 += __shfl_xor_sync(0xffffffffu, ls1, 1);
        ls1 += __shfl_xor_sync(0xffffffffu, ls1, 2);
        const float rl0 = __fdividef(1.f, ls0), rl1 = __fdividef(1.f, ls1);
        const int r0 = m0 + (lane >> 2);
        #pragma unroll
        for (int nc = 0; nc < 2; nc++) {
            const int col = 8 * nc + (lane & 3) * 2;
            *(float2*)(ts + r0 * 18 + col) = make_float2(acc[nc][0] * rl0, acc[nc][1] * rl0);
            *(float2*)(ts + (r0 + 8) * 18 + col) = make_float2(acc[nc][2] * rl1, acc[nc][3] * rl1);
        }
    }
    __syncthreads();

    #pragma unroll
    for (int pp = 0; pp < 2; pp++) {
        const int t = tid + pp * 128;
        float tv[16];
        const float* tr = ts + t * 18;
        #pragma unroll
        for (int j = 0; j < 8; j++) {
            float2 u = *(const float2*)(tr + 2 * j);
            tv[2*j] = u.x; tv[2*j+1] = u.y;
        }
        const float* xr = x + ((size_t)b << 22) + (size_t)f * 256 + t;
        __nv_bfloat16* zr = g_z + ((size_t)b << 22) + (size_t)f * 256 + t;
        #pragma unroll 4
        for (int c = 0; c < 64; c++) {
            const float* wr = wsp + c * 16;
            float s0 = 0.f, s1 = 0.f, s2 = 0.f, s3 = 0.f;
            #pragma unroll
            for (int j = 0; j < 4; j++) {
                s0 += wr[4*j]   * tv[4*j];
                s1 += wr[4*j+1] * tv[4*j+1];
                s2 += wr[4*j+2] * tv[4*j+2];
                s3 += wr[4*j+3] * tv[4*j+3];
            }
            float r = bsp[c] + ((s0 + s1) + (s2 + s3));
            r = (r >= 0.f) ? r : asp[c] * r;
            zr[(size_t)c << 16] = __float2bfloat16_rn(r + xr[(size_t)c << 16]);
        }
    }
}

// ============================================================================
// K4: LN + FFN, fp16 HMMA.  R14: combine R11's occupancy (16 warps) with
// R12's weight reuse (2 m-tiles/warp): 512 threads x 512-position tiles.
// Each weight B-fragment feeds 4 MMAs (2m x 2n) -> traffic halved vs R11,
// AND 16 warps/SM hide the LDSM latency (R12's regression cause).
// GELU in place on c1; hard-sigmoid; biases in accumulator init (proven).
// dyn smem: A @0 (512x144=73728); W1 @73728 (55296); W2 @129024 (50176).
// total 179200 B.  512 regs/thread cap: 96 accum/frag + temps ~= 120. OK.
// ============================================================================
#define OFF_A  0
#define OFF_W1 73728
#define OFF_W2 129024
#define FFN_DSMEM 179200

__global__ void __launch_bounds__(512) k_ffn_hmma(
    const float* __restrict__ x,
    const float* __restrict__ lnw, const float* __restrict__ lnb,
    const float* __restrict__ w1, const float* __restrict__ b1,
    const float* __restrict__ w2, const float* __restrict__ b2,
    const float* __restrict__ gamma, float* __restrict__ out)
{
    extern __shared__ char sm[];
    __shared__ uint32_t s_b1h2[192];    // b1 as half2 pairs
    __shared__ uint32_t s_b2h2[32];     // b2 as half2 pairs
    __shared__ float s_lnw[64], s_lnb[64], s_gm[64];

    const int tid = threadIdx.x;
    const int wid = tid >> 5;
    const int lane = tid & 31;
    const uint32_t sb = smem_u32(sm);

    for (int i = tid; i < 384 * 64; i += 512) {
        int o = i >> 6, c = i & 63;
        *(__half*)(sm + OFF_W1 + o * 144 + c * 2) = __float2half_rn(w1[i]);
    }
    for (int i = tid; i < 64 * 384; i += 512) {
        int c = i / 384, e = i % 384;
        *(__half*)(sm + OFF_W2 + c * 784 + e * 2) = __float2half_rn(w2[i]);
    }
    if (tid < 192) s_b1h2[tid] = hpack(b1[2 * tid], b1[2 * tid + 1]);
    if (tid < 32)  s_b2h2[tid] = hpack(b2[2 * tid], b2[2 * tid + 1]);
    if (tid < 64) { s_lnw[tid] = lnw[tid]; s_lnb[tid] = lnb[tid]; s_gm[tid] = gamma[tid]; }
    __syncthreads();

    const __half2 kA = __floats2half2_rn(0.4255f, 0.4255f);
    const __half2 kH = __floats2half2_rn(0.5f, 0.5f);

    for (int tile = blockIdx.x; tile < 512; tile += 148) {
        const int g0 = tile * 512;
        const int b = g0 >> 16;
        const int rbase = g0 & 65535;

        // ---- LN: 1 thread per position (warp-local rows) -> A smem fp16 ----
        {
            const int p = tid;
            const uint4* zp = (const uint4*)(g_z + ((size_t)b << 22) + (size_t)(rbase + p) * 64);
            uint32_t raw[32];
            float s = 0.f, ss = 0.f;
            #pragma unroll
            for (int j = 0; j < 8; j++) {
                uint4 u = zp[j];
                raw[4*j] = u.x; raw[4*j+1] = u.y; raw[4*j+2] = u.z; raw[4*j+3] = u.w;
                float2 f0 = bfunpack(u.x), f1 = bfunpack(u.y), f2 = bfunpack(u.z), f3 = bfunpack(u.w);
                s  += (f0.x + f0.y) + (f1.x + f1.y) + (f2.x + f2.y) + (f3.x + f3.y);
                ss += (f0.x*f0.x + f0.y*f0.y) + (f1.x*f1.x + f1.y*f1.y)
                    + (f2.x*f2.x + f2.y*f2.y) + (f3.x*f3.x + f3.y*f3.y);
            }
            float mu = s * (1.f / 64.f);
            float var = ss * (1.f / 64.f) - mu * mu;
            float rstd = rsqrtf(var + 1e-6f);

            char* ap = sm + OFF_A + p * 144;
            #pragma unroll
            for (int q = 0; q < 8; q++) {
                uint32_t pk[4];
                #pragma unroll
                for (int jj = 0; jj < 4; jj++) {
                    int pj = q * 4 + jj;
                    float2 fv = bfunpack(raw[pj]);
                    int c0 = 2 * pj;
                    float a0 = (fv.x - mu) * rstd * s_lnw[c0]     + s_lnb[c0];
                    float a1 = (fv.y - mu) * rstd * s_lnw[c0 + 1] + s_lnb[c0 + 1];
                    pk[jj] = hpack(a0, a1);
                }
                *(uint4*)(ap + q * 16) = make_uint4(pk[0], pk[1], pk[2], pk[3]);
            }
        }
        __syncwarp();

        // ---- A fragments: 2 m-tiles per warp (rows 32*wid .. 32*wid+31) ----
        uint32_t af[2][4][4];
        {
            #pragma unroll
            for (int m = 0; m < 2; m++) {
                const int arow = (2 * wid + m) * 16 + (lane & 7) + ((lane >> 3) & 1) * 8;
                #pragma unroll
                for (int ksp = 0; ksp < 4; ksp++) {
                    uint32_t acol = ksp * 16 + (lane >> 4) * 8;
                    ldm_x4(af[m][ksp], sb + OFF_A + arow * 144 + acol * 2);
                }
            }
        }

        // c2 accumulators (2 m-tiles), initialized with b2
        uint32_t c2[2][8][2];
        #pragma unroll
        for (int m = 0; m < 2; m++)
            #pragma unroll
            for (int i = 0; i < 8; i++) {
                uint32_t bv = s_b2h2[i * 4 + (lane & 3)];
                c2[m][i][0] = bv; c2[m][i][1] = bv;
            }

        #pragma unroll 1
        for (int ch = 0; ch < 6; ch++) {
            uint32_t c1[2][8][2];
            #pragma unroll
            for (int m = 0; m < 2; m++)
                #pragma unroll
                for (int i = 0; i < 8; i++) {
                    uint32_t bv = s_b1h2[ch * 32 + i * 4 + (lane & 3)];
                    c1[m][i][0] = bv; c1[m][i][1] = bv;
                }

            // GEMM1: each weight frag feeds 2m x 2n = 4 MMAs
            #pragma unroll
            for (int ksp = 0; ksp < 4; ksp++) {
                #pragma unroll
                for (int ntp = 0; ntp < 4; ntp++) {
                    uint32_t brow = (uint32_t)(ch * 64 + ntp * 16 + ((lane >> 4) & 1) * 8 + (lane & 7));
                    uint32_t bcol = (uint32_t)(ksp * 16 + ((lane >> 3) & 1) * 8);
                    uint32_t bfr[4];
                    ldm_x4(bfr, sb + OFF_W1 + brow * 144 + bcol * 2);
                    #pragma unroll
                    for (int m = 0; m < 2; m++) {
                        mma16816_h(c1[m][2 * ntp],     af[m][ksp], bfr);
                        mma16816_h(c1[m][2 * ntp + 1], af[m][ksp], bfr + 2);
                    }
                }
            }

            // hard-sigmoid GELU IN PLACE (c1 pair-layout == GEMM2 A-frag)
            #pragma unroll
            for (int m = 0; m < 2; m++)
                #pragma unroll
                for (int nt = 0; nt < 8; nt++)
                    #pragma unroll
                    for (int rr = 0; rr < 2; rr++) {
                        __half2 d = *(__half2*)&c1[m][nt][rr];
                        __half2 sg = __hfma2_sat(d, kA, kH);
                        __half2 hh = __hmul2(d, sg);
                        c1[m][nt][rr] = *(uint32_t*)&hh;
                    }

            // GEMM2: A-operand taken directly from c1 (contiguous 4 regs)
            #pragma unroll
            for (int j = 0; j < 4; j++) {
                #pragma unroll
                for (int ntp = 0; ntp < 4; ntp++) {
                    uint32_t brow = (uint32_t)(ntp * 16 + ((lane >> 4) & 1) * 8 + (lane & 7));
                    uint32_t bcol = (uint32_t)(ch * 64 + j * 16 + ((lane >> 3) & 1) * 8);
                    uint32_t bfr[4];
                    ldm_x4(bfr, sb + OFF_W2 + brow * 784 + bcol * 2);
                    #pragma unroll
                    for (int m = 0; m < 2; m++) {
                        mma16816_h(c2[m][2 * ntp],     &c1[m][2 * j][0], bfr);
                        mma16816_h(c2[m][2 * ntp + 1], &c1[m][2 * j][0], bfr + 2);
                    }
                }
            }
        }

        // ---- epilogue: out = x + gamma * c2  (b2 already inside c2) ----
        #pragma unroll
        for (int m = 0; m < 2; m++) {
            const int p0 = rbase + (2 * wid + m) * 16 + (lane >> 2);
            const int p1 = p0 + 8;
            const size_t bb = (size_t)b << 22;
            #pragma unroll
            for (int nt2 = 0; nt2 < 8; nt2++) {
                const int c0 = nt2 * 8 + (lane & 3) * 2;
                const int c1i = c0 + 1;
                float2 r0 = hunpack(c2[m][nt2][0]);
                float2 r1 = hunpack(c2[m][nt2][1]);
                const size_t a00 = bb + ((size_t)c0  << 16) + p0;
                const size_t a01 = bb + ((size_t)c1i << 16) + p0;
                const size_t a10 = bb + ((size_t)c0  << 16) + p1;
                const size_t a11 = bb + ((size_t)c1i << 16) + p1;
                out[a00] = x[a00] + s_gm[c0]  * r0.x;
                out[a01] = x[a01] + s_gm[c1i] * r0.y;
                out[a10] = x[a10] + s_gm[c0]  * r1.x;
                out[a11] = x[a11] + s_gm[c1i] * r1.y;
            }
        }
        __syncwarp();
    }
}

// ============================================================================
extern "C" void kernel_launch(void* const* d_in, const int* in_sizes, int n_in,
                              void* d_out, int out_size)
{
    const float* x   = (const float*)d_in[0];
    const float* wf  = (const float*)d_in[1];
    const float* f_g = (const float*)d_in[2];
    const float* f_b = (const float*)d_in[3];
    const float* f_m = (const float*)d_in[4];
    const float* f_v = (const float*)d_in[5];
    const float* f_a = (const float*)d_in[6];
    const float* wt  = (const float*)d_in[7];
    const float* t_g = (const float*)d_in[8];
    const float* t_b = (const float*)d_in[9];
    const float* t_m = (const float*)d_in[10];
    const float* t_v = (const float*)d_in[11];
    const float* t_a = (const float*)d_in[12];
    const float* wp  = (const float*)d_in[13];
    const float* p_g = (const float*)d_in[14];
    const float* p_b = (const float*)d_in[15];
    const float* p_m = (const float*)d_in[16];
    const float* p_v = (const float*)d_in[17];
    const float* p_a = (const float*)d_in[18];
    const float* lnw = (const float*)d_in[19];
    const float* lnb = (const float*)d_in[20];
    const float* w1  = (const float*)d_in[21];
    const float* b1  = (const float*)d_in[22];
    const float* w2  = (const float*)d_in[23];
    const float* b2  = (const float*)d_in[24];
    const float* gam = (const float*)d_in[25];
    float* out = (float*)d_out;

    cudaFuncSetAttribute(k_proj_mma, cudaFuncAttributeMaxDynamicSharedMemorySize, PROJ_DSMEM);
    cudaFuncSetAttribute(k_tattn_fused, cudaFuncAttributeMaxDynamicSharedMemorySize, TA_DSMEM);
    cudaFuncSetAttribute(k_ffn_hmma, cudaFuncAttributeMaxDynamicSharedMemorySize, FFN_DSMEM);

    k_proj_mma<<<BB * FF, 256, PROJ_DSMEM>>>(x, wf, f_g, f_b, f_m, f_v, f_a,
                                             wt, t_g, t_b, t_m, t_v, t_a);
    k_fattn_mma<<<BB * TT, 128>>>();
    k_tattn_fused<<<BB * FF, 128, TA_DSMEM>>>(x, wp, p_g, p_b, p_m, p_v, p_a);
    k_ffn_hmma<<<148, 512, FFN_DSMEM>>>(x, lnw, lnb, w1, b1, w2, b2, gam, out);
}

// round 15
// speedup vs baseline: 1.0410x; 1.0128x over previous
#include <cuda_runtime.h>
#include <cuda_bf16.h>
#include <cuda_fp16.h>
#include <cstddef>
#include <cstdint>

#define BB 4
#define CC 64
#define FF 256
#define TT 256

// ---- scratch (device globals; no allocation allowed) ----
// g_qf/g_kf/g_v: T-MAJOR bf16-pair layout [b][t][f] x 8 uint32  (R15)
// g_qt/g_kt/g_fo: position-major [b][f][t] x 8 uint32
__device__ uint32_t g_qf[BB*FF*TT*8];
__device__ uint32_t g_kf[BB*FF*TT*8];
__device__ uint32_t g_v [BB*FF*TT*8];
__device__ uint32_t g_qt[BB*FF*TT*8];
__device__ uint32_t g_kt[BB*FF*TT*8];
__device__ uint32_t g_fo[BB*FF*TT*8];
__device__ __nv_bfloat16 g_z[BB*CC*FF*TT];   // layout of x: [B,C,F,T], bf16

// ============================================================================
// base-ISA tensor helpers
// ============================================================================
__device__ __forceinline__ uint32_t smem_u32(const void* p) {
    uint32_t a;
    asm("{ .reg .u64 t; cvta.to.shared.u64 t, %1; cvt.u32.u64 %0, t; }" : "=r"(a) : "l"(p));
    return a;
}
__device__ __forceinline__ void mma16816(float* c, const uint32_t* a, const uint32_t* b) {
    asm volatile("mma.sync.aligned.m16n8k16.row.col.f32.bf16.bf16.f32 "
        "{%0,%1,%2,%3}, {%4,%5,%6,%7}, {%8,%9}, {%0,%1,%2,%3};"
        : "+f"(c[0]), "+f"(c[1]), "+f"(c[2]), "+f"(c[3])
        : "r"(a[0]), "r"(a[1]), "r"(a[2]), "r"(a[3]), "r"(b[0]), "r"(b[1]));
}
// fp16 in / fp16 accumulate: C = 2 packed half2 regs
__device__ __forceinline__ void mma16816_h(uint32_t* c, const uint32_t* a, const uint32_t* b) {
    asm volatile("mma.sync.aligned.m16n8k16.row.col.f16.f16.f16.f16 "
        "{%0,%1}, {%2,%3,%4,%5}, {%6,%7}, {%0,%1};"
        : "+r"(c[0]), "+r"(c[1])
        : "r"(a[0]), "r"(a[1]), "r"(a[2]), "r"(a[3]), "r"(b[0]), "r"(b[1]));
}
__device__ __forceinline__ void ldm_x4(uint32_t* r, uint32_t addr) {
    asm volatile("ldmatrix.sync.aligned.m8n8.x4.shared.b16 {%0,%1,%2,%3}, [%4];"
        : "=r"(r[0]), "=r"(r[1]), "=r"(r[2]), "=r"(r[3]) : "r"(addr));
}
__device__ __forceinline__ void ldm_x4_trans(uint32_t* r, uint32_t addr) {
    asm volatile("ldmatrix.sync.aligned.m8n8.x4.trans.shared.b16 {%0,%1,%2,%3}, [%4];"
        : "=r"(r[0]), "=r"(r[1]), "=r"(r[2]), "=r"(r[3]) : "r"(addr));
}
__device__ __forceinline__ void ldm_x2(uint32_t& r0, uint32_t& r1, uint32_t addr) {
    asm volatile("ldmatrix.sync.aligned.m8n8.x2.shared.b16 {%0,%1}, [%2];"
        : "=r"(r0), "=r"(r1) : "r"(addr));
}
__device__ __forceinline__ void ldm_x2_trans(uint32_t& r0, uint32_t& r1, uint32_t addr) {
    asm volatile("ldmatrix.sync.aligned.m8n8.x2.trans.shared.b16 {%0,%1}, [%2];"
        : "=r"(r0), "=r"(r1) : "r"(addr));
}
__device__ __forceinline__ uint32_t bfpack(float a, float b) {
    __nv_bfloat162 h = __floats2bfloat162_rn(a, b);
    return *(uint32_t*)&h;
}
__device__ __forceinline__ float2 bfunpack(uint32_t u) {
    return __bfloat1622float2(*(__nv_bfloat162*)&u);
}
__device__ __forceinline__ uint32_t hpack(float a, float b) {
    __half2 h = __floats2half2_rn(a, b);
    return *(uint32_t*)&h;
}
__device__ __forceinline__ float2 hunpack(uint32_t u) {
    return __half22float2(*(__half2*)&u);
}

// ============================================================================
// K1: projections on HMMA.  R15: qf/kf/v stored T-MAJOR (scatter on the
// store side, where it's absorbed by the store pipe); qt/kt position-major.
// ============================================================================
#define PROJ_CS 33792
#define PROJ_DSMEM (33792 + 45056)

__global__ void __launch_bounds__(256) k_proj_mma(
    const float* __restrict__ x,
    const float* __restrict__ wf, const float* __restrict__ fg, const float* __restrict__ fb,
    const float* __restrict__ fm, const float* __restrict__ fv, const float* __restrict__ fa,
    const float* __restrict__ wt, const float* __restrict__ tg, const float* __restrict__ tb,
    const float* __restrict__ tm, const float* __restrict__ tv, const float* __restrict__ ta)
{
    extern __shared__ char psm[];
    __shared__ __align__(16) char ws[80 * 144];
    __shared__ float bs[80], posw[80], slw[80];

    const int tid = threadIdx.x;
    const int wid = tid >> 5, lane = tid & 31;
    const uint32_t sxs = smem_u32(psm);
    const uint32_t sws = smem_u32(ws);

    for (int i = tid; i < 80 * 64; i += 256) {
        int o = i >> 6, c = i & 63;
        float g, b_, m, v, w;
        if (o < 48) { g = fg[o]; b_ = fb[o]; m = fm[o]; v = fv[o]; w = wf[o * 64 + c]; }
        else { int oo = o - 48; g = tg[oo]; b_ = tb[oo]; m = tm[oo]; v = tv[oo]; w = wt[oo * 64 + c]; }
        float inv = g * rsqrtf(v + 1e-5f);
        *(__nv_bfloat16*)(ws + o * 144 + c * 2) = __float2bfloat16_rn(w * inv);
        if (c == 0) {
            float slope = (o < 48) ? fa[o] : ta[o - 48];
            float sc = (o < 48) ? ((o % 3 == 0) ? 0.25f : 1.f)
                                : ((((o - 48) & 1) == 0) ? 0.25f : 1.f);
            bs[o] = b_ - m * inv;
            posw[o] = sc;
            slw[o] = slope * sc;
        }
    }

    const int bf = blockIdx.x;
    const int b = bf >> 8, f = bf & 255;
    {
        const int c = tid >> 2, q = tid & 3;
        const float* xp = x + ((size_t)b << 22) + ((size_t)c << 16) + (size_t)f * 256 + q * 64;
        char* row = psm + c * 528 + q * 128;
        #pragma unroll
        for (int j = 0; j < 8; j++) {
            float4 v0 = ((const float4*)xp)[2 * j];
            float4 v1 = ((const float4*)xp)[2 * j + 1];
            *(uint4*)(row + j * 16) = make_uint4(bfpack(v0.x, v0.y), bfpack(v0.z, v0.w),
                                                 bfpack(v1.x, v1.y), bfpack(v1.z, v1.w));
        }
    }
    __syncthreads();

    uint32_t af[2][4][4];
    {
        const int cr = (lane & 7) + ((lane >> 4) << 3);
        const int tof = ((lane >> 3) & 1) * 8;
        #pragma unroll
        for (int m = 0; m < 2; m++) {
            const int t0 = (2 * wid + m) * 16;
            #pragma unroll
            for (int ksp = 0; ksp < 4; ksp++)
                ldm_x4_trans(af[m][ksp], sxs + (uint32_t)((ksp * 16 + cr) * 528 + (t0 + tof) * 2));
        }
    }

    #pragma unroll 1
    for (int nt = 0; nt < 10; nt++) {
        uint32_t bfr[4][2];
        #pragma unroll
        for (int ksp = 0; ksp < 4; ksp++)
            ldm_x2(bfr[ksp][0], bfr[ksp][1],
                   sws + (uint32_t)((nt * 8 + (lane & 7)) * 144 + (ksp * 16 + ((lane >> 3) & 1) * 8) * 2));

        const int n0 = nt * 8 + (lane & 3) * 2;
        const float b0 = bs[n0], b1 = bs[n0 + 1];
        const float p0 = posw[n0], p1 = posw[n0 + 1];
        const float s0 = slw[n0], s1 = slw[n0 + 1];
        const int pairidx = nt * 4 + (lane & 3);

        #pragma unroll
        for (int m = 0; m < 2; m++) {
            float cfr[4] = {0.f, 0.f, 0.f, 0.f};
            #pragma unroll
            for (int ksp = 0; ksp < 4; ksp++) mma16816(cfr, af[m][ksp], bfr[ksp]);

            float r0 = cfr[0] + b0, r1 = cfr[1] + b1, r2 = cfr[2] + b0, r3 = cfr[3] + b1;
            r0 = (r0 >= 0.f) ? r0 * p0 : r0 * s0;
            r1 = (r1 >= 0.f) ? r1 * p1 : r1 * s1;
            r2 = (r2 >= 0.f) ? r2 * p0 : r2 * s0;
            r3 = (r3 >= 0.f) ? r3 * p1 : r3 * s1;

            const int tlo = (2 * wid + m) * 16 + (lane >> 2);
            *(uint32_t*)(psm + PROJ_CS + tlo * 176 + pairidx * 4) = bfpack(r0, r1);
            *(uint32_t*)(psm + PROJ_CS + (tlo + 8) * 176 + pairidx * 4) = bfpack(r2, r3);
        }
    }
    __syncthreads();

    {
        const int t = tid;
        uint32_t pr[40];
        const uint4* crow = (const uint4*)(psm + PROJ_CS + t * 176);
        #pragma unroll
        for (int j = 0; j < 10; j++) {
            uint4 u = crow[j];
            pr[4*j] = u.x; pr[4*j+1] = u.y; pr[4*j+2] = u.z; pr[4*j+3] = u.w;
        }
        uint32_t v16[80];
        #pragma unroll
        for (int j = 0; j < 40; j++) { v16[2*j] = pr[j] & 0xffffu; v16[2*j+1] = pr[j] >> 16; }

        const size_t pos  = (size_t)bf * 256 + t;                    // [b][f][t]
        const size_t posT = ((size_t)b * 256 + t) * 256 + f;         // [b][t][f]
        uint32_t o0[8], o1[8], o2[8], o3[8], o4[8];
        #pragma unroll
        for (int j = 0; j < 8; j++) {
            o0[j] = v16[6*j]     | (v16[6*j + 3] << 16);
            o1[j] = v16[6*j + 1] | (v16[6*j + 4] << 16);
            o2[j] = v16[6*j + 2] | (v16[6*j + 5] << 16);
            o3[j] = v16[48 + 4*j]     | (v16[48 + 4*j + 2] << 16);
            o4[j] = v16[48 + 4*j + 1] | (v16[48 + 4*j + 3] << 16);
        }
        ((uint4*)g_qf)[posT*2]   = make_uint4(o0[0], o0[1], o0[2], o0[3]);
        ((uint4*)g_qf)[posT*2+1] = make_uint4(o0[4], o0[5], o0[6], o0[7]);
        ((uint4*)g_kf)[posT*2]   = make_uint4(o1[0], o1[1], o1[2], o1[3]);
        ((uint4*)g_kf)[posT*2+1] = make_uint4(o1[4], o1[5], o1[6], o1[7]);
        ((uint4*)g_v )[posT*2]   = make_uint4(o2[0], o2[1], o2[2], o2[3]);
        ((uint4*)g_v )[posT*2+1] = make_uint4(o2[4], o2[5], o2[6], o2[7]);
        ((uint4*)g_qt)[pos*2]    = make_uint4(o3[0], o3[1], o3[2], o3[3]);
        ((uint4*)g_qt)[pos*2+1]  = make_uint4(o3[4], o3[5], o3[6], o3[7]);
        ((uint4*)g_kt)[pos*2]    = make_uint4(o4[0], o4[1], o4[2], o4[3]);
        ((uint4*)g_kt)[pos*2+1]  = make_uint4(o4[4], o4[5], o4[6], o4[7]);
    }
}

// ============================================================================
// K2: frequency attention (HMMA).  R15: q/k/v now T-MAJOR — the entire
// 24KB staging is three contiguous 8KB streams (coalesced uint2 copies).
// ============================================================================
__global__ void __launch_bounds__(128) k_fattn_mma()
{
    __shared__ __align__(16) char qs[256 * 48];
    __shared__ __align__(16) char ks[256 * 48];
    __shared__ __align__(16) char vs[256 * 48];

    const int bt = blockIdx.x;
    const int b = bt >> 8, t = bt & 255;
    const int tid = threadIdx.x;
    const int wid = tid >> 5, lane = tid & 31;
    const uint32_t svs = smem_u32(vs);

    // ---- stage (contiguous): rows f of 4 uint2 each; base = (b*256+t)*1024 ----
    {
        const uint2* gq = (const uint2*)g_qf + ((size_t)(b * 256 + t)) * 1024;
        const uint2* gk = (const uint2*)g_kf + ((size_t)(b * 256 + t)) * 1024;
        const uint2* gv = (const uint2*)g_v  + ((size_t)(b * 256 + t)) * 1024;
        #pragma unroll
        for (int i = tid; i < 1024; i += 128) {
            const int r = i >> 2, q = i & 3;
            *(uint2*)(qs + r * 48 + q * 8) = gq[i];
            *(uint2*)(ks + r * 48 + q * 8) = gk[i];
            *(uint2*)(vs + r * 48 + q * 8) = gv[i];
        }
    }
    __syncthreads();

    uint32_t qa[4][4];
    {
        const uint32_t rb = (lane >> 2), cb = (lane & 3) * 4;
        #pragma unroll
        for (int mt = 0; mt < 4; mt++) {
            const uint32_t m0 = wid * 64 + mt * 16;
            qa[mt][0] = *(const uint32_t*)(qs + (m0 + rb) * 48 + cb);
            qa[mt][1] = *(const uint32_t*)(qs + (m0 + 8 + rb) * 48 + cb);
            qa[mt][2] = *(const uint32_t*)(qs + (m0 + rb) * 48 + cb + 16);
            qa[mt][3] = *(const uint32_t*)(qs + (m0 + 8 + rb) * 48 + cb + 16);
        }
    }

    float acc[4][2][4];
    float ls[4][2];
    #pragma unroll
    for (int mt = 0; mt < 4; mt++) {
        ls[mt][0] = ls[mt][1] = 0.f;
        #pragma unroll
        for (int nc = 0; nc < 2; nc++)
            #pragma unroll
            for (int k = 0; k < 4; k++) acc[mt][nc][k] = 0.f;
    }

    for (int yt = 0; yt < 8; yt++) {
        const int y0 = yt * 32;
        uint32_t kb[4][2];
        #pragma unroll
        for (int j = 0; j < 4; j++) {
            const char* a = ks + (y0 + 8 * j + (lane >> 2)) * 48 + (lane & 3) * 4;
            kb[j][0] = *(const uint32_t*)a;
            kb[j][1] = *(const uint32_t*)(a + 16);
        }
        uint32_t vb[2][2][2];
        #pragma unroll
        for (int kst = 0; kst < 2; kst++)
            #pragma unroll
            for (int nc = 0; nc < 2; nc++)
                ldm_x2_trans(vb[kst][nc][0], vb[kst][nc][1],
                             svs + (uint32_t)((y0 + 16 * kst + (lane & 15)) * 48 + nc * 16));

        #pragma unroll
        for (int mt = 0; mt < 4; mt++) {
            float s[4][4];
            #pragma unroll
            for (int j = 0; j < 4; j++) { s[j][0]=s[j][1]=s[j][2]=s[j][3]=0.f; }
            #pragma unroll
            for (int j = 0; j < 4; j++) mma16816(s[j], qa[mt], kb[j]);

            float p[4][4];
            #pragma unroll
            for (int j = 0; j < 4; j++) {
                p[j][0] = __expf(s[j][0]); p[j][1] = __expf(s[j][1]);
                p[j][2] = __expf(s[j][2]); p[j][3] = __expf(s[j][3]);
                ls[mt][0] += p[j][0] + p[j][1];
                ls[mt][1] += p[j][2] + p[j][3];
            }
            uint32_t pa0[4], pa1[4];
            pa0[0] = bfpack(p[0][0], p[0][1]); pa0[1] = bfpack(p[0][2], p[0][3]);
            pa0[2] = bfpack(p[1][0], p[1][1]); pa0[3] = bfpack(p[1][2], p[1][3]);
            pa1[0] = bfpack(p[2][0], p[2][1]); pa1[1] = bfpack(p[2][2], p[2][3]);
            pa1[2] = bfpack(p[3][0], p[3][1]); pa1[3] = bfpack(p[3][2], p[3][3]);
            #pragma unroll
            for (int nc = 0; nc < 2; nc++) {
                mma16816(acc[mt][nc], pa0, vb[0][nc]);
                mma16816(acc[mt][nc], pa1, vb[1][nc]);
            }
        }
    }

    // ---- epilogue: normalize, pack bf16, store to g_fo [b][f][t] ----
    #pragma unroll
    for (int mt = 0; mt < 4; mt++) {
        float l0 = ls[mt][0], l1 = ls[mt][1];
        l0 += __shfl_xor_sync(0xffffffffu, l0, 1);
        l0 += __shfl_xor_sync(0xffffffffu, l0, 2);
        l1 += __shfl_xor_sync(0xffffffffu, l1, 1);
        l1 += __shfl_xor_sync(0xffffffffu, l1, 2);
        const float rl0 = __fdividef(1.f, l0), rl1 = __fdividef(1.f, l1);
        const int r0 = wid * 64 + mt * 16 + (lane >> 2);
        #pragma unroll
        for (int nc = 0; nc < 2; nc++) {
            const int pidx = nc * 4 + (lane & 3);
            g_fo[((size_t)b * 65536 + (size_t)r0 * 256 + t) * 8 + pidx] =
                bfpack(acc[mt][nc][0] * rl0, acc[mt][nc][1] * rl0);
            g_fo[((size_t)b * 65536 + (size_t)(r0 + 8) * 256 + t) * 8 + pidx] =
                bfpack(acc[mt][nc][2] * rl1, acc[mt][nc][3] * rl1);
        }
    }
}

// ============================================================================
// K3: causal time attention + zproj fusion.  (unchanged — layouts unaffected)
// ============================================================================
#define TA_KS 12288
#define TA_VS 24576
#define TA_TS 36864
#define TA_WSP 55296
#define TA_BSP 59392
#define TA_ASP 59648
#define TA_DSMEM 59904

__global__ void __launch_bounds__(128) k_tattn_fused(
    const float* __restrict__ x, const float* __restrict__ wp,
    const float* __restrict__ pg, const float* __restrict__ pb,
    const float* __restrict__ pm, const float* __restrict__ pv,
    const float* __restrict__ pa)
{
    extern __shared__ char dsm[];
    char* qs = dsm;
    char* ks = dsm + TA_KS;
    char* vs = dsm + TA_VS;
    float* ts = (float*)(dsm + TA_TS);
    float* wsp = (float*)(dsm + TA_WSP);
    float* bsp = (float*)(dsm + TA_BSP);
    float* asp = (float*)(dsm + TA_ASP);

    const int bf = blockIdx.x;
    const int b = bf >> 8, f = bf & 255;
    const int tid = threadIdx.x;
    const int wid = tid >> 5, lane = tid & 31;
    const uint32_t svs = smem_u32(vs);

    {
        const uint2* gq = (const uint2*)g_qt + (size_t)bf * 1024;
        const uint2* gk = (const uint2*)g_kt + (size_t)bf * 1024;
        const uint2* gv = (const uint2*)g_fo + (size_t)bf * 1024;
        #pragma unroll
        for (int i = tid; i < 1024; i += 128) {
            const int r = i >> 2, q = i & 3;
            *(uint2*)(qs + r * 48 + q * 8) = gq[i];
            *(uint2*)(ks + r * 48 + q * 8) = gk[i];
            *(uint2*)(vs + r * 48 + q * 8) = gv[i];
        }
        for (int i = tid; i < 1024; i += 128) {
            const int o = i >> 4, k = i & 15;
            float inv = pg[o] * rsqrtf(pv[o] + 1e-5f);
            wsp[o * 16 + k] = wp[o * 16 + k] * inv;
            if (k == 0) { bsp[o] = pb[o] - pm[o] * inv; asp[o] = pa[o]; }
        }
    }
    __syncthreads();

    #pragma unroll 1
    for (int i = 0; i < 4; i++) {
        const int mt = wid + 4 * i;
        const int m0 = mt * 16;
        uint32_t qa[4];
        {
            const uint32_t rb = (lane >> 2), cb = (lane & 3) * 4;
            qa[0] = *(const uint32_t*)(qs + (m0 + rb) * 48 + cb);
            qa[1] = *(const uint32_t*)(qs + (m0 + 8 + rb) * 48 + cb);
            qa[2] = *(const uint32_t*)(qs + (m0 + rb) * 48 + cb + 16);
            qa[3] = *(const uint32_t*)(qs + (m0 + 8 + rb) * 48 + cb + 16);
        }
        float acc[2][4] = {{0.f,0.f,0.f,0.f},{0.f,0.f,0.f,0.f}};
        float ls0 = 0.f, ls1 = 0.f;
        const int nyt = (mt >> 1) + 1;

        for (int yt = 0; yt < nyt; yt++) {
            const int y0 = yt * 32;
            uint32_t kb[4][2];
            #pragma unroll
            for (int j = 0; j < 4; j++) {
                const char* a = ks + (y0 + 8 * j + (lane >> 2)) * 48 + (lane & 3) * 4;
                kb[j][0] = *(const uint32_t*)a;
                kb[j][1] = *(const uint32_t*)(a + 16);
            }
            uint32_t vb[2][2][2];
            #pragma unroll
            for (int kst = 0; kst < 2; kst++)
                #pragma unroll
                for (int nc = 0; nc < 2; nc++)
                    ldm_x2_trans(vb[kst][nc][0], vb[kst][nc][1],
                                 svs + (uint32_t)((y0 + 16 * kst + (lane & 15)) * 48 + nc * 16));

            float s[4][4];
            #pragma unroll
            for (int j = 0; j < 4; j++) { s[j][0]=s[j][1]=s[j][2]=s[j][3]=0.f; }
            #pragma unroll
            for (int j = 0; j < 4; j++) mma16816(s[j], qa, kb[j]);

            if (yt == nyt - 1) {
                const int r0 = m0 + (lane >> 2);
                #pragma unroll
                for (int j = 0; j < 4; j++) {
                    const int cb2 = y0 + 8 * j + (lane & 3) * 2;
                    if (cb2     > r0)     s[j][0] = -1e30f;
                    if (cb2 + 1 > r0)     s[j][1] = -1e30f;
                    if (cb2     > r0 + 8) s[j][2] = -1e30f;
                    if (cb2 + 1 > r0 + 8) s[j][3] = -1e30f;
                }
            }

            float p[4][4];
            #pragma unroll
            for (int j = 0; j < 4; j++) {
                p[j][0] = __expf(s[j][0]); p[j][1] = __expf(s[j][1]);
                p[j][2] = __expf(s[j][2]); p[j][3] = __expf(s[j][3]);
                ls0 += p[j][0] + p[j][1];
                ls1 += p[j][2] + p[j][3];
            }
            uint32_t pa0[4], pa1[4];
            pa0[0] = bfpack(p[0][0], p[0][1]); pa0[1] = bfpack(p[0][2], p[0][3]);
            pa0[2] = bfpack(p[1][0], p[1][1]); pa0[3] = bfpack(p[1][2], p[1][3]);
            pa1[0] = bfpack(p[2][0], p[2][1]); pa1[1] = bfpack(p[2][2], p[2][3]);
            pa1[2] = bfpack(p[3][0], p[3][1]); pa1[3] = bfpack(p[3][2], p[3][3]);
            #pragma unroll
            for (int nc = 0; nc < 2; nc++) {
                mma16816(acc[nc], pa0, vb[0][nc]);
                mma16816(acc[nc], pa1, vb[1][nc]);
            }
        }

        ls0 += __shfl_xor_sync(0xffffffffu, ls0, 1);
        ls0 += __shfl_xor_sync(0xffffffffu, ls0, 2);
        ls1 += __shfl_xor_sync(0xffffffffu, ls1, 1);
        ls1 += __shfl_xor_sync(0xffffffffu, ls1, 2);
        const float rl0 = __fdividef(1.f, ls0), rl1 = __fdividef(1.f, ls1);
        const int r0 = m0 + (lane >> 2);
        #pragma unroll
        for (int nc = 0; nc < 2; nc++) {
            const int col = 8 * nc + (lane & 3) * 2;
            *(float2*)(ts + r0 * 18 + col) = make_float2(acc[nc][0] * rl0, acc[nc][1] * rl0);
            *(float2*)(ts + (r0 + 8) * 18 + col) = make_float2(acc[nc][2] * rl1, acc[nc][3] * rl1);
        }
    }
    __syncthreads();

    #pragma unroll
    for (int pp = 0; pp < 2; pp++) {
        const int t = tid + pp * 128;
        float tv[16];
        const float* tr = ts + t * 18;
        #pragma unroll
        for (int j = 0; j < 8; j++) {
            float2 u = *(const float2*)(tr + 2 * j);
            tv[2*j] = u.x; tv[2*j+1] = u.y;
        }
        const float* xr = x + ((size_t)b << 22) + (size_t)f * 256 + t;
        __nv_bfloat16* zr = g_z + ((size_t)b << 22) + (size_t)f * 256 + t;
        #pragma unroll 4
        for (int c = 0; c < 64; c++) {
            const float* wr = wsp + c * 16;
            float s0 = 0.f, s1 = 0.f, s2 = 0.f, s3 = 0.f;
            #pragma unroll
            for (int j = 0; j < 4; j++) {
                s0 += wr[4*j]   * tv[4*j];
                s1 += wr[4*j+1] * tv[4*j+1];
                s2 += wr[4*j+2] * tv[4*j+2];
                s3 += wr[4*j+3] * tv[4*j+3];
            }
            float r = bsp[c] + ((s0 + s1) + (s2 + s3));
            r = (r >= 0.f) ? r : asp[c] * r;
            zr[(size_t)c << 16] = __float2bfloat16_rn(r + xr[(size_t)c << 16]);
        }
    }
}

// ============================================================================
// K4: LN + FFN, fp16 HMMA.  (unchanged from R14 — 92.0us measured)
// 512 threads x 512-position tiles; 2 m-tiles/warp weight reuse; hard-sigmoid
// GELU in place on c1; biases folded into accumulator init.
// ============================================================================
#define OFF_A  0
#define OFF_W1 73728
#define OFF_W2 129024
#define FFN_DSMEM 179200

__global__ void __launch_bounds__(512) k_ffn_hmma(
    const float* __restrict__ x,
    const float* __restrict__ lnw, const float* __restrict__ lnb,
    const float* __restrict__ w1, const float* __restrict__ b1,
    const float* __restrict__ w2, const float* __restrict__ b2,
    const float* __restrict__ gamma, float* __restrict__ out)
{
    extern __shared__ char sm[];
    __shared__ uint32_t s_b1h2[192];
    __shared__ uint32_t s_b2h2[32];
    __shared__ float s_lnw[64], s_lnb[64], s_gm[64];

    const int tid = threadIdx.x;
    const int wid = tid >> 5;
    const int lane = tid & 31;
    const uint32_t sb = smem_u32(sm);

    for (int i = tid; i < 384 * 64; i += 512) {
        int o = i >> 6, c = i & 63;
        *(__half*)(sm + OFF_W1 + o * 144 + c * 2) = __float2half_rn(w1[i]);
    }
    for (int i = tid; i < 64 * 384; i += 512) {
        int c = i / 384, e = i % 384;
        *(__half*)(sm + OFF_W2 + c * 784 + e * 2) = __float2half_rn(w2[i]);
    }
    if (tid < 192) s_b1h2[tid] = hpack(b1[2 * tid], b1[2 * tid + 1]);
    if (tid < 32)  s_b2h2[tid] = hpack(b2[2 * tid], b2[2 * tid + 1]);
    if (tid < 64) { s_lnw[tid] = lnw[tid]; s_lnb[tid] = lnb[tid]; s_gm[tid] = gamma[tid]; }
    __syncthreads();

    const __half2 kA = __floats2half2_rn(0.4255f, 0.4255f);
    const __half2 kH = __floats2half2_rn(0.5f, 0.5f);

    for (int tile = blockIdx.x; tile < 512; tile += 148) {
        const int g0 = tile * 512;
        const int b = g0 >> 16;
        const int rbase = g0 & 65535;

        {
            const int p = tid;
            const uint4* zp = (const uint4*)(g_z + ((size_t)b << 22) + (size_t)(rbase + p) * 64);
            uint32_t raw[32];
            float s = 0.f, ss = 0.f;
            #pragma unroll
            for (int j = 0; j < 8; j++) {
                uint4 u = zp[j];
                raw[4*j] = u.x; raw[4*j+1] = u.y; raw[4*j+2] = u.z; raw[4*j+3] = u.w;
                float2 f0 = bfunpack(u.x), f1 = bfunpack(u.y), f2 = bfunpack(u.z), f3 = bfunpack(u.w);
                s  += (f0.x + f0.y) + (f1.x + f1.y) + (f2.x + f2.y) + (f3.x + f3.y);
                ss += (f0.x*f0.x + f0.y*f0.y) + (f1.x*f1.x + f1.y*f1.y)
                    + (f2.x*f2.x + f2.y*f2.y) + (f3.x*f3.x + f3.y*f3.y);
            }
            float mu = s * (1.f / 64.f);
            float var = ss * (1.f / 64.f) - mu * mu;
            float rstd = rsqrtf(var + 1e-6f);

            char* ap = sm + OFF_A + p * 144;
            #pragma unroll
            for (int q = 0; q < 8; q++) {
                uint32_t pk[4];
                #pragma unroll
                for (int jj = 0; jj < 4; jj++) {
                    int pj = q * 4 + jj;
                    float2 fv = bfunpack(raw[pj]);
                    int c0 = 2 * pj;
                    float a0 = (fv.x - mu) * rstd * s_lnw[c0]     + s_lnb[c0];
                    float a1 = (fv.y - mu) * rstd * s_lnw[c0 + 1] + s_lnb[c0 + 1];
                    pk[jj] = hpack(a0, a1);
                }
                *(uint4*)(ap + q * 16) = make_uint4(pk[0], pk[1], pk[2], pk[3]);
            }
        }
        __syncwarp();

        uint32_t af[2][4][4];
        {
            #pragma unroll
            for (int m = 0; m < 2; m++) {
                const int arow = (2 * wid + m) * 16 + (lane & 7) + ((lane >> 3) & 1) * 8;
                #pragma unroll
                for (int ksp = 0; ksp < 4; ksp++) {
                    uint32_t acol = ksp * 16 + (lane >> 4) * 8;
                    ldm_x4(af[m][ksp], sb + OFF_A + arow * 144 + acol * 2);
                }
            }
        }

        uint32_t c2[2][8][2];
        #pragma unroll
        for (int m = 0; m < 2; m++)
            #pragma unroll
            for (int i = 0; i < 8; i++) {
                uint32_t bv = s_b2h2[i * 4 + (lane & 3)];
                c2[m][i][0] = bv; c2[m][i][1] = bv;
            }

        #pragma unroll 1
        for (int ch = 0; ch < 6; ch++) {
            uint32_t c1[2][8][2];
            #pragma unroll
            for (int m = 0; m < 2; m++)
                #pragma unroll
                for (int i = 0; i < 8; i++) {
                    uint32_t bv = s_b1h2[ch * 32 + i * 4 + (lane & 3)];
                    c1[m][i][0] = bv; c1[m][i][1] = bv;
                }

            #pragma unroll
            for (int ksp = 0; ksp < 4; ksp++) {
                #pragma unroll
                for (int ntp = 0; ntp < 4; ntp++) {
                    uint32_t brow = (uint32_t)(ch * 64 + ntp * 16 + ((lane >> 4) & 1) * 8 + (lane & 7));
                    uint32_t bcol = (uint32_t)(ksp * 16 + ((lane >> 3) & 1) * 8);
                    uint32_t bfr[4];
                    ldm_x4(bfr, sb + OFF_W1 + brow * 144 + bcol * 2);
                    #pragma unroll
                    for (int m = 0; m < 2; m++) {
                        mma16816_h(c1[m][2 * ntp],     af[m][ksp], bfr);
                        mma16816_h(c1[m][2 * ntp + 1], af[m][ksp], bfr + 2);
                    }
                }
            }

            #pragma unroll
            for (int m = 0; m < 2; m++)
                #pragma unroll
                for (int nt = 0; nt < 8; nt++)
                    #pragma unroll
                    for (int rr = 0; rr < 2; rr++) {
                        __half2 d = *(__half2*)&c1[m][nt][rr];
                        __half2 sg = __hfma2_sat(d, kA, kH);
                        __half2 hh = __hmul2(d, sg);
                        c1[m][nt][rr] = *(uint32_t*)&hh;
                    }

            #pragma unroll
            for (int j = 0; j < 4; j++) {
                #pragma unroll
                for (int ntp = 0; ntp < 4; ntp++) {
                    uint32_t brow = (uint32_t)(ntp * 16 + ((lane >> 4) & 1) * 8 + (lane & 7));
                    uint32_t bcol = (uint32_t)(ch * 64 + j * 16 + ((lane >> 3) & 1) * 8);
                    uint32_t bfr[4];
                    ldm_x4(bfr, sb + OFF_W2 + brow * 784 + bcol * 2);
                    #pragma unroll
                    for (int m = 0; m < 2; m++) {
                        mma16816_h(c2[m][2 * ntp],     &c1[m][2 * j][0], bfr);
                        mma16816_h(c2[m][2 * ntp + 1], &c1[m][2 * j][0], bfr + 2);
                    }
                }
            }
        }

        #pragma unroll
        for (int m = 0; m < 2; m++) {
            const int p0 = rbase + (2 * wid + m) * 16 + (lane >> 2);
            const int p1 = p0 + 8;
            const size_t bb = (size_t)b << 22;
            #pragma unroll
            for (int nt2 = 0; nt2 < 8; nt2++) {
                const int c0 = nt2 * 8 + (lane & 3) * 2;
                const int c1i = c0 + 1;
                float2 r0 = hunpack(c2[m][nt2][0]);
                float2 r1 = hunpack(c2[m][nt2][1]);
                const size_t a00 = bb + ((size_t)c0  << 16) + p0;
                const size_t a01 = bb + ((size_t)c1i << 16) + p0;
                const size_t a10 = bb + ((size_t)c0  << 16) + p1;
                const size_t a11 = bb + ((size_t)c1i << 16) + p1;
                out[a00] = x[a00] + s_gm[c0]  * r0.x;
                out[a01] = x[a01] + s_gm[c1i] * r0.y;
                out[a10] = x[a10] + s_gm[c0]  * r1.x;
                out[a11] = x[a11] + s_gm[c1i] * r1.y;
            }
        }
        __syncwarp();
    }
}

// ============================================================================
extern "C" void kernel_launch(void* const* d_in, const int* in_sizes, int n_in,
                              void* d_out, int out_size)
{
    const float* x   = (const float*)d_in[0];
    const float* wf  = (const float*)d_in[1];
    const float* f_g = (const float*)d_in[2];
    const float* f_b = (const float*)d_in[3];
    const float* f_m = (const float*)d_in[4];
    const float* f_v = (const float*)d_in[5];
    const float* f_a = (const float*)d_in[6];
    const float* wt  = (const float*)d_in[7];
    const float* t_g = (const float*)d_in[8];
    const float* t_b = (const float*)d_in[9];
    const float* t_m = (const float*)d_in[10];
    const float* t_v = (const float*)d_in[11];
    const float* t_a = (const float*)d_in[12];
    const float* wp  = (const float*)d_in[13];
    const float* p_g = (const float*)d_in[14];
    const float* p_b = (const float*)d_in[15];
    const float* p_m = (const float*)d_in[16];
    const float* p_v = (const float*)d_in[17];
    const float* p_a = (const float*)d_in[18];
    const float* lnw = (const float*)d_in[19];
    const float* lnb = (const float*)d_in[20];
    const float* w1  = (const float*)d_in[21];
    const float* b1  = (const float*)d_in[22];
    const float* w2  = (const float*)d_in[23];
    const float* b2  = (const float*)d_in[24];
    const float* gam = (const float*)d_in[25];
    float* out = (float*)d_out;

    cudaFuncSetAttribute(k_proj_mma, cudaFuncAttributeMaxDynamicSharedMemorySize, PROJ_DSMEM);
    cudaFuncSetAttribute(k_tattn_fused, cudaFuncAttributeMaxDynamicSharedMemorySize, TA_DSMEM);
    cudaFuncSetAttribute(k_ffn_hmma, cudaFuncAttributeMaxDynamicSharedMemorySize, FFN_DSMEM);

    k_proj_mma<<<BB * FF, 256, PROJ_DSMEM>>>(x, wf, f_g, f_b, f_m, f_v, f_a,
                                             wt, t_g, t_b, t_m, t_v, t_a);
    k_fattn_mma<<<BB * TT, 128>>>();
    k_tattn_fused<<<BB * FF, 128, TA_DSMEM>>>(x, wp, p_g, p_b, p_m, p_v, p_a);
    k_ffn_hmma<<<148, 512, FFN_DSMEM>>>(x, lnw, lnb, w1, b1, w2, b2, gam, out);
}

// round 16
// speedup vs baseline: 1.1652x; 1.1193x over previous
#include <cuda_runtime.h>
#include <cuda_bf16.h>
#include <cuda_fp16.h>
#include <cstddef>
#include <cstdint>

#define BB 4
#define CC 64
#define FF 256
#define TT 256

// ---- scratch (device globals; no allocation allowed) ----
// g_qf/g_kf/g_v: T-MAJOR bf16-pair layout [b][t][f] x 8 uint32
// g_qt/g_kt/g_fo: position-major [b][f][t] x 8 uint32
__device__ uint32_t g_qf[BB*FF*TT*8];
__device__ uint32_t g_kf[BB*FF*TT*8];
__device__ uint32_t g_v [BB*FF*TT*8];
__device__ uint32_t g_qt[BB*FF*TT*8];
__device__ uint32_t g_kt[BB*FF*TT*8];
__device__ uint32_t g_fo[BB*FF*TT*8];
__device__ __nv_bfloat16 g_z[BB*CC*FF*TT];   // layout of x: [B,C,F,T], bf16

// ============================================================================
// base-ISA tensor helpers
// ============================================================================
__device__ __forceinline__ uint32_t smem_u32(const void* p) {
    uint32_t a;
    asm("{ .reg .u64 t; cvta.to.shared.u64 t, %1; cvt.u32.u64 %0, t; }" : "=r"(a) : "l"(p));
    return a;
}
__device__ __forceinline__ void mma16816(float* c, const uint32_t* a, const uint32_t* b) {
    asm volatile("mma.sync.aligned.m16n8k16.row.col.f32.bf16.bf16.f32 "
        "{%0,%1,%2,%3}, {%4,%5,%6,%7}, {%8,%9}, {%0,%1,%2,%3};"
        : "+f"(c[0]), "+f"(c[1]), "+f"(c[2]), "+f"(c[3])
        : "r"(a[0]), "r"(a[1]), "r"(a[2]), "r"(a[3]), "r"(b[0]), "r"(b[1]));
}
// fp16 in / fp16 accumulate: C = 2 packed half2 regs
__device__ __forceinline__ void mma16816_h(uint32_t* c, const uint32_t* a, const uint32_t* b) {
    asm volatile("mma.sync.aligned.m16n8k16.row.col.f16.f16.f16.f16 "
        "{%0,%1}, {%2,%3,%4,%5}, {%6,%7}, {%0,%1};"
        : "+r"(c[0]), "+r"(c[1])
        : "r"(a[0]), "r"(a[1]), "r"(a[2]), "r"(a[3]), "r"(b[0]), "r"(b[1]));
}
__device__ __forceinline__ void ldm_x4(uint32_t* r, uint32_t addr) {
    asm volatile("ldmatrix.sync.aligned.m8n8.x4.shared.b16 {%0,%1,%2,%3}, [%4];"
        : "=r"(r[0]), "=r"(r[1]), "=r"(r[2]), "=r"(r[3]) : "r"(addr));
}
__device__ __forceinline__ void ldm_x4_trans(uint32_t* r, uint32_t addr) {
    asm volatile("ldmatrix.sync.aligned.m8n8.x4.trans.shared.b16 {%0,%1,%2,%3}, [%4];"
        : "=r"(r[0]), "=r"(r[1]), "=r"(r[2]), "=r"(r[3]) : "r"(addr));
}
__device__ __forceinline__ void ldm_x2(uint32_t& r0, uint32_t& r1, uint32_t addr) {
    asm volatile("ldmatrix.sync.aligned.m8n8.x2.shared.b16 {%0,%1}, [%2];"
        : "=r"(r0), "=r"(r1) : "r"(addr));
}
__device__ __forceinline__ void ldm_x2_trans(uint32_t& r0, uint32_t& r1, uint32_t addr) {
    asm volatile("ldmatrix.sync.aligned.m8n8.x2.trans.shared.b16 {%0,%1}, [%2];"
        : "=r"(r0), "=r"(r1) : "r"(addr));
}
__device__ __forceinline__ uint32_t bfpack(float a, float b) {
    __nv_bfloat162 h = __floats2bfloat162_rn(a, b);
    return *(uint32_t*)&h;
}
__device__ __forceinline__ float2 bfunpack(uint32_t u) {
    return __bfloat1622float2(*(__nv_bfloat162*)&u);
}
__device__ __forceinline__ uint32_t hpack(float a, float b) {
    __half2 h = __floats2half2_rn(a, b);
    return *(uint32_t*)&h;
}
__device__ __forceinline__ float2 hunpack(uint32_t u) {
    return __half22float2(*(__half2*)&u);
}

// ============================================================================
// K1: projections on HMMA.  (unchanged from R15)
// ============================================================================
#define PROJ_CS 33792
#define PROJ_DSMEM (33792 + 45056)

__global__ void __launch_bounds__(256) k_proj_mma(
    const float* __restrict__ x,
    const float* __restrict__ wf, const float* __restrict__ fg, const float* __restrict__ fb,
    const float* __restrict__ fm, const float* __restrict__ fv, const float* __restrict__ fa,
    const float* __restrict__ wt, const float* __restrict__ tg, const float* __restrict__ tb,
    const float* __restrict__ tm, const float* __restrict__ tv, const float* __restrict__ ta)
{
    extern __shared__ char psm[];
    __shared__ __align__(16) char ws[80 * 144];
    __shared__ float bs[80], posw[80], slw[80];

    const int tid = threadIdx.x;
    const int wid = tid >> 5, lane = tid & 31;
    const uint32_t sxs = smem_u32(psm);
    const uint32_t sws = smem_u32(ws);

    for (int i = tid; i < 80 * 64; i += 256) {
        int o = i >> 6, c = i & 63;
        float g, b_, m, v, w;
        if (o < 48) { g = fg[o]; b_ = fb[o]; m = fm[o]; v = fv[o]; w = wf[o * 64 + c]; }
        else { int oo = o - 48; g = tg[oo]; b_ = tb[oo]; m = tm[oo]; v = tv[oo]; w = wt[oo * 64 + c]; }
        float inv = g * rsqrtf(v + 1e-5f);
        *(__nv_bfloat16*)(ws + o * 144 + c * 2) = __float2bfloat16_rn(w * inv);
        if (c == 0) {
            float slope = (o < 48) ? fa[o] : ta[o - 48];
            float sc = (o < 48) ? ((o % 3 == 0) ? 0.25f : 1.f)
                                : ((((o - 48) & 1) == 0) ? 0.25f : 1.f);
            bs[o] = b_ - m * inv;
            posw[o] = sc;
            slw[o] = slope * sc;
        }
    }

    const int bf = blockIdx.x;
    const int b = bf >> 8, f = bf & 255;
    {
        const int c = tid >> 2, q = tid & 3;
        const float* xp = x + ((size_t)b << 22) + ((size_t)c << 16) + (size_t)f * 256 + q * 64;
        char* row = psm + c * 528 + q * 128;
        #pragma unroll
        for (int j = 0; j < 8; j++) {
            float4 v0 = ((const float4*)xp)[2 * j];
            float4 v1 = ((const float4*)xp)[2 * j + 1];
            *(uint4*)(row + j * 16) = make_uint4(bfpack(v0.x, v0.y), bfpack(v0.z, v0.w),
                                                 bfpack(v1.x, v1.y), bfpack(v1.z, v1.w));
        }
    }
    __syncthreads();

    uint32_t af[2][4][4];
    {
        const int cr = (lane & 7) + ((lane >> 4) << 3);
        const int tof = ((lane >> 3) & 1) * 8;
        #pragma unroll
        for (int m = 0; m < 2; m++) {
            const int t0 = (2 * wid + m) * 16;
            #pragma unroll
            for (int ksp = 0; ksp < 4; ksp++)
                ldm_x4_trans(af[m][ksp], sxs + (uint32_t)((ksp * 16 + cr) * 528 + (t0 + tof) * 2));
        }
    }

    #pragma unroll 1
    for (int nt = 0; nt < 10; nt++) {
        uint32_t bfr[4][2];
        #pragma unroll
        for (int ksp = 0; ksp < 4; ksp++)
            ldm_x2(bfr[ksp][0], bfr[ksp][1],
                   sws + (uint32_t)((nt * 8 + (lane & 7)) * 144 + (ksp * 16 + ((lane >> 3) & 1) * 8) * 2));

        const int n0 = nt * 8 + (lane & 3) * 2;
        const float b0 = bs[n0], b1 = bs[n0 + 1];
        const float p0 = posw[n0], p1 = posw[n0 + 1];
        const float s0 = slw[n0], s1 = slw[n0 + 1];
        const int pairidx = nt * 4 + (lane & 3);

        #pragma unroll
        for (int m = 0; m < 2; m++) {
            float cfr[4] = {0.f, 0.f, 0.f, 0.f};
            #pragma unroll
            for (int ksp = 0; ksp < 4; ksp++) mma16816(cfr, af[m][ksp], bfr[ksp]);

            float r0 = cfr[0] + b0, r1 = cfr[1] + b1, r2 = cfr[2] + b0, r3 = cfr[3] + b1;
            r0 = (r0 >= 0.f) ? r0 * p0 : r0 * s0;
            r1 = (r1 >= 0.f) ? r1 * p1 : r1 * s1;
            r2 = (r2 >= 0.f) ? r2 * p0 : r2 * s0;
            r3 = (r3 >= 0.f) ? r3 * p1 : r3 * s1;

            const int tlo = (2 * wid + m) * 16 + (lane >> 2);
            *(uint32_t*)(psm + PROJ_CS + tlo * 176 + pairidx * 4) = bfpack(r0, r1);
            *(uint32_t*)(psm + PROJ_CS + (tlo + 8) * 176 + pairidx * 4) = bfpack(r2, r3);
        }
    }
    __syncthreads();

    {
        const int t = tid;
        uint32_t pr[40];
        const uint4* crow = (const uint4*)(psm + PROJ_CS + t * 176);
        #pragma unroll
        for (int j = 0; j < 10; j++) {
            uint4 u = crow[j];
            pr[4*j] = u.x; pr[4*j+1] = u.y; pr[4*j+2] = u.z; pr[4*j+3] = u.w;
        }
        uint32_t v16[80];
        #pragma unroll
        for (int j = 0; j < 40; j++) { v16[2*j] = pr[j] & 0xffffu; v16[2*j+1] = pr[j] >> 16; }

        const size_t pos  = (size_t)bf * 256 + t;                    // [b][f][t]
        const size_t posT = ((size_t)b * 256 + t) * 256 + f;         // [b][t][f]
        uint32_t o0[8], o1[8], o2[8], o3[8], o4[8];
        #pragma unroll
        for (int j = 0; j < 8; j++) {
            o0[j] = v16[6*j]     | (v16[6*j + 3] << 16);
            o1[j] = v16[6*j + 1] | (v16[6*j + 4] << 16);
            o2[j] = v16[6*j + 2] | (v16[6*j + 5] << 16);
            o3[j] = v16[48 + 4*j]     | (v16[48 + 4*j + 2] << 16);
            o4[j] = v16[48 + 4*j + 1] | (v16[48 + 4*j + 3] << 16);
        }
        ((uint4*)g_qf)[posT*2]   = make_uint4(o0[0], o0[1], o0[2], o0[3]);
        ((uint4*)g_qf)[posT*2+1] = make_uint4(o0[4], o0[5], o0[6], o0[7]);
        ((uint4*)g_kf)[posT*2]   = make_uint4(o1[0], o1[1], o1[2], o1[3]);
        ((uint4*)g_kf)[posT*2+1] = make_uint4(o1[4], o1[5], o1[6], o1[7]);
        ((uint4*)g_v )[posT*2]   = make_uint4(o2[0], o2[1], o2[2], o2[3]);
        ((uint4*)g_v )[posT*2+1] = make_uint4(o2[4], o2[5], o2[6], o2[7]);
        ((uint4*)g_qt)[pos*2]    = make_uint4(o3[0], o3[1], o3[2], o3[3]);
        ((uint4*)g_qt)[pos*2+1]  = make_uint4(o3[4], o3[5], o3[6], o3[7]);
        ((uint4*)g_kt)[pos*2]    = make_uint4(o4[0], o4[1], o4[2], o4[3]);
        ((uint4*)g_kt)[pos*2+1]  = make_uint4(o4[4], o4[5], o4[6], o4[7]);
    }
}

// ============================================================================
// K2: frequency attention (HMMA).  (unchanged from R15 — T-major staging)
// ============================================================================
__global__ void __launch_bounds__(128) k_fattn_mma()
{
    __shared__ __align__(16) char qs[256 * 48];
    __shared__ __align__(16) char ks[256 * 48];
    __shared__ __align__(16) char vs[256 * 48];

    const int bt = blockIdx.x;
    const int b = bt >> 8, t = bt & 255;
    const int tid = threadIdx.x;
    const int wid = tid >> 5, lane = tid & 31;
    const uint32_t svs = smem_u32(vs);

    {
        const uint2* gq = (const uint2*)g_qf + ((size_t)(b * 256 + t)) * 1024;
        const uint2* gk = (const uint2*)g_kf + ((size_t)(b * 256 + t)) * 1024;
        const uint2* gv = (const uint2*)g_v  + ((size_t)(b * 256 + t)) * 1024;
        #pragma unroll
        for (int i = tid; i < 1024; i += 128) {
            const int r = i >> 2, q = i & 3;
            *(uint2*)(qs + r * 48 + q * 8) = gq[i];
            *(uint2*)(ks + r * 48 + q * 8) = gk[i];
            *(uint2*)(vs + r * 48 + q * 8) = gv[i];
        }
    }
    __syncthreads();

    uint32_t qa[4][4];
    {
        const uint32_t rb = (lane >> 2), cb = (lane & 3) * 4;
        #pragma unroll
        for (int mt = 0; mt < 4; mt++) {
            const uint32_t m0 = wid * 64 + mt * 16;
            qa[mt][0] = *(const uint32_t*)(qs + (m0 + rb) * 48 + cb);
            qa[mt][1] = *(const uint32_t*)(qs + (m0 + 8 + rb) * 48 + cb);
            qa[mt][2] = *(const uint32_t*)(qs + (m0 + rb) * 48 + cb + 16);
            qa[mt][3] = *(const uint32_t*)(qs + (m0 + 8 + rb) * 48 + cb + 16);
        }
    }

    float acc[4][2][4];
    float ls[4][2];
    #pragma unroll
    for (int mt = 0; mt < 4; mt++) {
        ls[mt][0] = ls[mt][1] = 0.f;
        #pragma unroll
        for (int nc = 0; nc < 2; nc++)
            #pragma unroll
            for (int k = 0; k < 4; k++) acc[mt][nc][k] = 0.f;
    }

    for (int yt = 0; yt < 8; yt++) {
        const int y0 = yt * 32;
        uint32_t kb[4][2];
        #pragma unroll
        for (int j = 0; j < 4; j++) {
            const char* a = ks + (y0 + 8 * j + (lane >> 2)) * 48 + (lane & 3) * 4;
            kb[j][0] = *(const uint32_t*)a;
            kb[j][1] = *(const uint32_t*)(a + 16);
        }
        uint32_t vb[2][2][2];
        #pragma unroll
        for (int kst = 0; kst < 2; kst++)
            #pragma unroll
            for (int nc = 0; nc < 2; nc++)
                ldm_x2_trans(vb[kst][nc][0], vb[kst][nc][1],
                             svs + (uint32_t)((y0 + 16 * kst + (lane & 15)) * 48 + nc * 16));

        #pragma unroll
        for (int mt = 0; mt < 4; mt++) {
            float s[4][4];
            #pragma unroll
            for (int j = 0; j < 4; j++) { s[j][0]=s[j][1]=s[j][2]=s[j][3]=0.f; }
            #pragma unroll
            for (int j = 0; j < 4; j++) mma16816(s[j], qa[mt], kb[j]);

            float p[4][4];
            #pragma unroll
            for (int j = 0; j < 4; j++) {
                p[j][0] = __expf(s[j][0]); p[j][1] = __expf(s[j][1]);
                p[j][2] = __expf(s[j][2]); p[j][3] = __expf(s[j][3]);
                ls[mt][0] += p[j][0] + p[j][1];
                ls[mt][1] += p[j][2] + p[j][3];
            }
            uint32_t pa0[4], pa1[4];
            pa0[0] = bfpack(p[0][0], p[0][1]); pa0[1] = bfpack(p[0][2], p[0][3]);
            pa0[2] = bfpack(p[1][0], p[1][1]); pa0[3] = bfpack(p[1][2], p[1][3]);
            pa1[0] = bfpack(p[2][0], p[2][1]); pa1[1] = bfpack(p[2][2], p[2][3]);
            pa1[2] = bfpack(p[3][0], p[3][1]); pa1[3] = bfpack(p[3][2], p[3][3]);
            #pragma unroll
            for (int nc = 0; nc < 2; nc++) {
                mma16816(acc[mt][nc], pa0, vb[0][nc]);
                mma16816(acc[mt][nc], pa1, vb[1][nc]);
            }
        }
    }

    #pragma unroll
    for (int mt = 0; mt < 4; mt++) {
        float l0 = ls[mt][0], l1 = ls[mt][1];
        l0 += __shfl_xor_sync(0xffffffffu, l0, 1);
        l0 += __shfl_xor_sync(0xffffffffu, l0, 2);
        l1 += __shfl_xor_sync(0xffffffffu, l1, 1);
        l1 += __shfl_xor_sync(0xffffffffu, l1, 2);
        const float rl0 = __fdividef(1.f, l0), rl1 = __fdividef(1.f, l1);
        const int r0 = wid * 64 + mt * 16 + (lane >> 2);
        #pragma unroll
        for (int nc = 0; nc < 2; nc++) {
            const int pidx = nc * 4 + (lane & 3);
            g_fo[((size_t)b * 65536 + (size_t)r0 * 256 + t) * 8 + pidx] =
                bfpack(acc[mt][nc][0] * rl0, acc[mt][nc][1] * rl0);
            g_fo[((size_t)b * 65536 + (size_t)(r0 + 8) * 256 + t) * 8 + pidx] =
                bfpack(acc[mt][nc][2] * rl1, acc[mt][nc][3] * rl1);
        }
    }
}

// ============================================================================
// K3: causal time attention + HMMA zproj (R16).
// The attention C-fragment (normalized) IS the zproj A-fragment, so the
// 2048-FMA scalar dot product becomes 8 ldm_x2 + 8 mma per m-tile, fused
// in registers.  bias/PReLU on C-frags; z bounced through smem bf16 [t][c]
// rows (c,c+1 adjacent -> packed 4B stores) for a coalesced final x+store.
// dyn smem: qs@0 ks@12288 vs@24576 (48B rows); zs@36864 (256x144B);
//           wsp2@73728 (64x48B n-major bf16); bsp@76800; asp@77056. tot 77312
// ============================================================================
#define TA_KS 12288
#define TA_VS 24576
#define TA_ZS 36864
#define TA_WS2 73728
#define TA_BSP 76800
#define TA_ASP 77056
#define TA_DSMEM 77312

__global__ void __launch_bounds__(128) k_tattn_fused(
    const float* __restrict__ x, const float* __restrict__ wp,
    const float* __restrict__ pg, const float* __restrict__ pb,
    const float* __restrict__ pm, const float* __restrict__ pv,
    const float* __restrict__ pa)
{
    extern __shared__ char dsm[];
    char* qs = dsm;
    char* ks = dsm + TA_KS;
    char* vs = dsm + TA_VS;
    char* zs = dsm + TA_ZS;                   // [256 t][144B: 64 bf16 + pad]
    float* bsp = (float*)(dsm + TA_BSP);
    float* asp = (float*)(dsm + TA_ASP);

    const int bf = blockIdx.x;
    const int b = bf >> 8, f = bf & 255;
    const int tid = threadIdx.x;
    const int wid = tid >> 5, lane = tid & 31;
    const uint32_t svs = smem_u32(vs);
    const uint32_t sws2 = smem_u32(dsm + TA_WS2);

    // ---- stage q/k/v tiles + folded zproj weights (bf16 n-major, 48B rows) --
    {
        const uint2* gq = (const uint2*)g_qt + (size_t)bf * 1024;
        const uint2* gk = (const uint2*)g_kt + (size_t)bf * 1024;
        const uint2* gv = (const uint2*)g_fo + (size_t)bf * 1024;
        #pragma unroll
        for (int i = tid; i < 1024; i += 128) {
            const int r = i >> 2, q = i & 3;
            *(uint2*)(qs + r * 48 + q * 8) = gq[i];
            *(uint2*)(ks + r * 48 + q * 8) = gk[i];
            *(uint2*)(vs + r * 48 + q * 8) = gv[i];
        }
        for (int i = tid; i < 1024; i += 128) {
            const int o = i >> 4, k = i & 15;
            float inv = pg[o] * rsqrtf(pv[o] + 1e-5f);
            *(__nv_bfloat16*)(dsm + TA_WS2 + o * 48 + k * 2) =
                __float2bfloat16_rn(wp[o * 16 + k] * inv);
            if (k == 0) { bsp[o] = pb[o] - pm[o] * inv; asp[o] = pa[o]; }
        }
    }
    __syncthreads();

    // ---- preload wp B-frags (8 n-tiles x 2 regs, k=16 single step) ----
    uint32_t wb[8][2];
    #pragma unroll
    for (int nt = 0; nt < 8; nt++)
        ldm_x2(wb[nt][0], wb[nt][1],
               sws2 + (uint32_t)((nt * 8 + (lane & 7)) * 48 + ((lane >> 3) & 1) * 16));

    #pragma unroll 1
    for (int i = 0; i < 4; i++) {
        const int mt = wid + 4 * i;
        const int m0 = mt * 16;
        uint32_t qa[4];
        {
            const uint32_t rb = (lane >> 2), cb = (lane & 3) * 4;
            qa[0] = *(const uint32_t*)(qs + (m0 + rb) * 48 + cb);
            qa[1] = *(const uint32_t*)(qs + (m0 + 8 + rb) * 48 + cb);
            qa[2] = *(const uint32_t*)(qs + (m0 + rb) * 48 + cb + 16);
            qa[3] = *(const uint32_t*)(qs + (m0 + 8 + rb) * 48 + cb + 16);
        }
        float acc[2][4] = {{0.f,0.f,0.f,0.f},{0.f,0.f,0.f,0.f}};
        float ls0 = 0.f, ls1 = 0.f;
        const int nyt = (mt >> 1) + 1;

        for (int yt = 0; yt < nyt; yt++) {
            const int y0 = yt * 32;
            uint32_t kb[4][2];
            #pragma unroll
            for (int j = 0; j < 4; j++) {
                const char* a = ks + (y0 + 8 * j + (lane >> 2)) * 48 + (lane & 3) * 4;
                kb[j][0] = *(const uint32_t*)a;
                kb[j][1] = *(const uint32_t*)(a + 16);
            }
            uint32_t vb[2][2][2];
            #pragma unroll
            for (int kst = 0; kst < 2; kst++)
                #pragma unroll
                for (int nc = 0; nc < 2; nc++)
                    ldm_x2_trans(vb[kst][nc][0], vb[kst][nc][1],
                                 svs + (uint32_t)((y0 + 16 * kst + (lane & 15)) * 48 + nc * 16));

            float s[4][4];
            #pragma unroll
            for (int j = 0; j < 4; j++) { s[j][0]=s[j][1]=s[j][2]=s[j][3]=0.f; }
            #pragma unroll
            for (int j = 0; j < 4; j++) mma16816(s[j], qa, kb[j]);

            if (yt == nyt - 1) {   // diagonal tile: mask col > row
                const int r0 = m0 + (lane >> 2);
                #pragma unroll
                for (int j = 0; j < 4; j++) {
                    const int cb2 = y0 + 8 * j + (lane & 3) * 2;
                    if (cb2     > r0)     s[j][0] = -1e30f;
                    if (cb2 + 1 > r0)     s[j][1] = -1e30f;
                    if (cb2     > r0 + 8) s[j][2] = -1e30f;
                    if (cb2 + 1 > r0 + 8) s[j][3] = -1e30f;
                }
            }

            float p[4][4];
            #pragma unroll
            for (int j = 0; j < 4; j++) {
                p[j][0] = __expf(s[j][0]); p[j][1] = __expf(s[j][1]);
                p[j][2] = __expf(s[j][2]); p[j][3] = __expf(s[j][3]);
                ls0 += p[j][0] + p[j][1];
                ls1 += p[j][2] + p[j][3];
            }
            uint32_t pa0[4], pa1[4];
            pa0[0] = bfpack(p[0][0], p[0][1]); pa0[1] = bfpack(p[0][2], p[0][3]);
            pa0[2] = bfpack(p[1][0], p[1][1]); pa0[3] = bfpack(p[1][2], p[1][3]);
            pa1[0] = bfpack(p[2][0], p[2][1]); pa1[1] = bfpack(p[2][2], p[2][3]);
            pa1[2] = bfpack(p[3][0], p[3][1]); pa1[3] = bfpack(p[3][2], p[3][3]);
            #pragma unroll
            for (int nc = 0; nc < 2; nc++) {
                mma16816(acc[nc], pa0, vb[0][nc]);
                mma16816(acc[nc], pa1, vb[1][nc]);
            }
        }

        ls0 += __shfl_xor_sync(0xffffffffu, ls0, 1);
        ls0 += __shfl_xor_sync(0xffffffffu, ls0, 2);
        ls1 += __shfl_xor_sync(0xffffffffu, ls1, 1);
        ls1 += __shfl_xor_sync(0xffffffffu, ls1, 2);
        const float rl0 = __fdividef(1.f, ls0), rl1 = __fdividef(1.f, ls1);

        // ---- zproj on HMMA: attention C-frag (normalized) == A-frag ----
        uint32_t ta2[4];
        ta2[0] = bfpack(acc[0][0] * rl0, acc[0][1] * rl0);   // row r0,  k 2(lane&3),+1
        ta2[1] = bfpack(acc[0][2] * rl1, acc[0][3] * rl1);   // row r0+8
        ta2[2] = bfpack(acc[1][0] * rl0, acc[1][1] * rl0);   // row r0,  k+8
        ta2[3] = bfpack(acc[1][2] * rl1, acc[1][3] * rl1);   // row r0+8

        const int r0 = m0 + (lane >> 2);
        #pragma unroll
        for (int nt = 0; nt < 8; nt++) {
            const int c0 = nt * 8 + (lane & 3) * 2;
            float zacc[4];
            zacc[0] = bsp[c0]; zacc[1] = bsp[c0 + 1];
            zacc[2] = bsp[c0]; zacc[3] = bsp[c0 + 1];
            mma16816(zacc, ta2, wb[nt]);
            const float a0 = asp[c0], a1 = asp[c0 + 1];
            float v0 = (zacc[0] >= 0.f) ? zacc[0] : a0 * zacc[0];
            float v1 = (zacc[1] >= 0.f) ? zacc[1] : a1 * zacc[1];
            float v2 = (zacc[2] >= 0.f) ? zacc[2] : a0 * zacc[2];
            float v3 = (zacc[3] >= 0.f) ? zacc[3] : a1 * zacc[3];
            *(uint32_t*)(zs + r0 * 144 + c0 * 2) = bfpack(v0, v1);
            *(uint32_t*)(zs + (r0 + 8) * 144 + c0 * 2) = bfpack(v2, v3);
        }
    }
    __syncthreads();

    // ---- final: g_z = zs + x  (coalesced across t) ----
    #pragma unroll
    for (int pp = 0; pp < 2; pp++) {
        const int t = tid + pp * 128;
        uint32_t zr32[32];
        const uint4* zrow = (const uint4*)(zs + t * 144);
        #pragma unroll
        for (int q = 0; q < 8; q++) {
            uint4 u = zrow[q];
            zr32[4*q] = u.x; zr32[4*q+1] = u.y; zr32[4*q+2] = u.z; zr32[4*q+3] = u.w;
        }
        const float* xr = x + ((size_t)b << 22) + (size_t)f * 256 + t;
        __nv_bfloat16* zg = g_z + ((size_t)b << 22) + (size_t)f * 256 + t;
        #pragma unroll
        for (int j = 0; j < 32; j++) {
            float2 zv = bfunpack(zr32[j]);
            const int c0 = 2 * j;
            zg[(size_t)c0 << 16]       = __float2bfloat16_rn(zv.x + xr[(size_t)c0 << 16]);
            zg[(size_t)(c0 + 1) << 16] = __float2bfloat16_rn(zv.y + xr[(size_t)(c0 + 1) << 16]);
        }
    }
}

// ============================================================================
// K4: LN + FFN, fp16 HMMA.  (unchanged from R14 — 92.0us measured)
// ============================================================================
#define OFF_A  0
#define OFF_W1 73728
#define OFF_W2 129024
#define FFN_DSMEM 179200

__global__ void __launch_bounds__(512) k_ffn_hmma(
    const float* __restrict__ x,
    const float* __restrict__ lnw, const float* __restrict__ lnb,
    const float* __restrict__ w1, const float* __restrict__ b1,
    const float* __restrict__ w2, const float* __restrict__ b2,
    const float* __restrict__ gamma, float* __restrict__ out)
{
    extern __shared__ char sm[];
    __shared__ uint32_t s_b1h2[192];
    __shared__ uint32_t s_b2h2[32];
    __shared__ float s_lnw[64], s_lnb[64], s_gm[64];

    const int tid = threadIdx.x;
    const int wid = tid >> 5;
    const int lane = tid & 31;
    const uint32_t sb = smem_u32(sm);

    for (int i = tid; i < 384 * 64; i += 512) {
        int o = i >> 6, c = i & 63;
        *(__half*)(sm + OFF_W1 + o * 144 + c * 2) = __float2half_rn(w1[i]);
    }
    for (int i = tid; i < 64 * 384; i += 512) {
        int c = i / 384, e = i % 384;
        *(__half*)(sm + OFF_W2 + c * 784 + e * 2) = __float2half_rn(w2[i]);
    }
    if (tid < 192) s_b1h2[tid] = hpack(b1[2 * tid], b1[2 * tid + 1]);
    if (tid < 32)  s_b2h2[tid] = hpack(b2[2 * tid], b2[2 * tid + 1]);
    if (tid < 64) { s_lnw[tid] = lnw[tid]; s_lnb[tid] = lnb[tid]; s_gm[tid] = gamma[tid]; }
    __syncthreads();

    const __half2 kA = __floats2half2_rn(0.4255f, 0.4255f);
    const __half2 kH = __floats2half2_rn(0.5f, 0.5f);

    for (int tile = blockIdx.x; tile < 512; tile += 148) {
        const int g0 = tile * 512;
        const int b = g0 >> 16;
        const int rbase = g0 & 65535;

        {
            const int p = tid;
            const uint4* zp = (const uint4*)(g_z + ((size_t)b << 22) + (size_t)(rbase + p) * 64);
            uint32_t raw[32];
            float s = 0.f, ss = 0.f;
            #pragma unroll
            for (int j = 0; j < 8; j++) {
                uint4 u = zp[j];
                raw[4*j] = u.x; raw[4*j+1] = u.y; raw[4*j+2] = u.z; raw[4*j+3] = u.w;
                float2 f0 = bfunpack(u.x), f1 = bfunpack(u.y), f2 = bfunpack(u.z), f3 = bfunpack(u.w);
                s  += (f0.x + f0.y) + (f1.x + f1.y) + (f2.x + f2.y) + (f3.x + f3.y);
                ss += (f0.x*f0.x + f0.y*f0.y) + (f1.x*f1.x + f1.y*f1.y)
                    + (f2.x*f2.x + f2.y*f2.y) + (f3.x*f3.x + f3.y*f3.y);
            }
            float mu = s * (1.f / 64.f);
            float var = ss * (1.f / 64.f) - mu * mu;
            float rstd = rsqrtf(var + 1e-6f);

            char* ap = sm + OFF_A + p * 144;
            #pragma unroll
            for (int q = 0; q < 8; q++) {
                uint32_t pk[4];
                #pragma unroll
                for (int jj = 0; jj < 4; jj++) {
                    int pj = q * 4 + jj;
                    float2 fv = bfunpack(raw[pj]);
                    int c0 = 2 * pj;
                    float a0 = (fv.x - mu) * rstd * s_lnw[c0]     + s_lnb[c0];
                    float a1 = (fv.y - mu) * rstd * s_lnw[c0 + 1] + s_lnb[c0 + 1];
                    pk[jj] = hpack(a0, a1);
                }
                *(uint4*)(ap + q * 16) = make_uint4(pk[0], pk[1], pk[2], pk[3]);
            }
        }
        __syncwarp();

        uint32_t af[2][4][4];
        {
            #pragma unroll
            for (int m = 0; m < 2; m++) {
                const int arow = (2 * wid + m) * 16 + (lane & 7) + ((lane >> 3) & 1) * 8;
                #pragma unroll
                for (int ksp = 0; ksp < 4; ksp++) {
                    uint32_t acol = ksp * 16 + (lane >> 4) * 8;
                    ldm_x4(af[m][ksp], sb + OFF_A + arow * 144 + acol * 2);
                }
            }
        }

        uint32_t c2[2][8][2];
        #pragma unroll
        for (int m = 0; m < 2; m++)
            #pragma unroll
            for (int i = 0; i < 8; i++) {
                uint32_t bv = s_b2h2[i * 4 + (lane & 3)];
                c2[m][i][0] = bv; c2[m][i][1] = bv;
            }

        #pragma unroll 1
        for (int ch = 0; ch < 6; ch++) {
            uint32_t c1[2][8][2];
            #pragma unroll
            for (int m = 0; m < 2; m++)
                #pragma unroll
                for (int i = 0; i < 8; i++) {
                    uint32_t bv = s_b1h2[ch * 32 + i * 4 + (lane & 3)];
                    c1[m][i][0] = bv; c1[m][i][1] = bv;
                }

            #pragma unroll
            for (int ksp = 0; ksp < 4; ksp++) {
                #pragma unroll
                for (int ntp = 0; ntp < 4; ntp++) {
                    uint32_t brow = (uint32_t)(ch * 64 + ntp * 16 + ((lane >> 4) & 1) * 8 + (lane & 7));
                    uint32_t bcol = (uint32_t)(ksp * 16 + ((lane >> 3) & 1) * 8);
                    uint32_t bfr[4];
                    ldm_x4(bfr, sb + OFF_W1 + brow * 144 + bcol * 2);
                    #pragma unroll
                    for (int m = 0; m < 2; m++) {
                        mma16816_h(c1[m][2 * ntp],     af[m][ksp], bfr);
                        mma16816_h(c1[m][2 * ntp + 1], af[m][ksp], bfr + 2);
                    }
                }
            }

            #pragma unroll
            for (int m = 0; m < 2; m++)
                #pragma unroll
                for (int nt = 0; nt < 8; nt++)
                    #pragma unroll
                    for (int rr = 0; rr < 2; rr++) {
                        __half2 d = *(__half2*)&c1[m][nt][rr];
                        __half2 sg = __hfma2_sat(d, kA, kH);
                        __half2 hh = __hmul2(d, sg);
                        c1[m][nt][rr] = *(uint32_t*)&hh;
                    }

            #pragma unroll
            for (int j = 0; j < 4; j++) {
                #pragma unroll
                for (int ntp = 0; ntp < 4; ntp++) {
                    uint32_t brow = (uint32_t)(ntp * 16 + ((lane >> 4) & 1) * 8 + (lane & 7));
                    uint32_t bcol = (uint32_t)(ch * 64 + j * 16 + ((lane >> 3) & 1) * 8);
                    uint32_t bfr[4];
                    ldm_x4(bfr, sb + OFF_W2 + brow * 784 + bcol * 2);
                    #pragma unroll
                    for (int m = 0; m < 2; m++) {
                        mma16816_h(c2[m][2 * ntp],     &c1[m][2 * j][0], bfr);
                        mma16816_h(c2[m][2 * ntp + 1], &c1[m][2 * j][0], bfr + 2);
                    }
                }
            }
        }

        #pragma unroll
        for (int m = 0; m < 2; m++) {
            const int p0 = rbase + (2 * wid + m) * 16 + (lane >> 2);
            const int p1 = p0 + 8;
            const size_t bb = (size_t)b << 22;
            #pragma unroll
            for (int nt2 = 0; nt2 < 8; nt2++) {
                const int c0 = nt2 * 8 + (lane & 3) * 2;
                const int c1i = c0 + 1;
                float2 r0 = hunpack(c2[m][nt2][0]);
                float2 r1 = hunpack(c2[m][nt2][1]);
                const size_t a00 = bb + ((size_t)c0  << 16) + p0;
                const size_t a01 = bb + ((size_t)c1i << 16) + p0;
                const size_t a10 = bb + ((size_t)c0  << 16) + p1;
                const size_t a11 = bb + ((size_t)c1i << 16) + p1;
                out[a00] = x[a00] + s_gm[c0]  * r0.x;
                out[a01] = x[a01] + s_gm[c1i] * r0.y;
                out[a10] = x[a10] + s_gm[c0]  * r1.x;
                out[a11] = x[a11] + s_gm[c1i] * r1.y;
            }
        }
        __syncwarp();
    }
}

// ============================================================================
extern "C" void kernel_launch(void* const* d_in, const int* in_sizes, int n_in,
                              void* d_out, int out_size)
{
    const float* x   = (const float*)d_in[0];
    const float* wf  = (const float*)d_in[1];
    const float* f_g = (const float*)d_in[2];
    const float* f_b = (const float*)d_in[3];
    const float* f_m = (const float*)d_in[4];
    const float* f_v = (const float*)d_in[5];
    const float* f_a = (const float*)d_in[6];
    const float* wt  = (const float*)d_in[7];
    const float* t_g = (const float*)d_in[8];
    const float* t_b = (const float*)d_in[9];
    const float* t_m = (const float*)d_in[10];
    const float* t_v = (const float*)d_in[11];
    const float* t_a = (const float*)d_in[12];
    const float* wp  = (const float*)d_in[13];
    const float* p_g = (const float*)d_in[14];
    const float* p_b = (const float*)d_in[15];
    const float* p_m = (const float*)d_in[16];
    const float* p_v = (const float*)d_in[17];
    const float* p_a = (const float*)d_in[18];
    const float* lnw = (const float*)d_in[19];
    const float* lnb = (const float*)d_in[20];
    const float* w1  = (const float*)d_in[21];
    const float* b1  = (const float*)d_in[22];
    const float* w2  = (const float*)d_in[23];
    const float* b2  = (const float*)d_in[24];
    const float* gam = (const float*)d_in[25];
    float* out = (float*)d_out;

    cudaFuncSetAttribute(k_proj_mma, cudaFuncAttributeMaxDynamicSharedMemorySize, PROJ_DSMEM);
    cudaFuncSetAttribute(k_tattn_fused, cudaFuncAttributeMaxDynamicSharedMemorySize, TA_DSMEM);
    cudaFuncSetAttribute(k_ffn_hmma, cudaFuncAttributeMaxDynamicSharedMemorySize, FFN_DSMEM);

    k_proj_mma<<<BB * FF, 256, PROJ_DSMEM>>>(x, wf, f_g, f_b, f_m, f_v, f_a,
                                             wt, t_g, t_b, t_m, t_v, t_a);
    k_fattn_mma<<<BB * TT, 128>>>();
    k_tattn_fused<<<BB * FF, 128, TA_DSMEM>>>(x, wp, p_g, p_b, p_m, p_v, p_a);
    k_ffn_hmma<<<148, 512, FFN_DSMEM>>>(x, lnw, lnb, w1, b1, w2, b2, gam, out);
}